// round 11
// baseline (speedup 1.0000x reference)
#include <cuda_runtime.h>
#include <cuda_fp16.h>
#include <cstdint>
#include <math.h>

#define Bb 4
#define Tt 1024
#define Ee 512
#define Hh 8
#define Dd 64
#define Ff 2048
#define NROWS (Bb*Tt)
#define SCALE 0.125f
#define LN_EPS 1e-5f

// ================= device scratch (all 16-bit buffers are fp16) ===========
__device__ __align__(16) float g_Y [NROWS*Ee];
__device__ __align__(16) float g_X1[NROWS*Ee];
__device__ __align__(16) float g_X2[NROWS*Ee];
__device__ __align__(16) float g_BcatS[1536];
__device__ __align__(16) float g_BcatC[1024];
__device__ __align__(16) __half g_TH  [NROWS*Ee];
__device__ __align__(16) __half g_MH  [NROWS*Ee];
__device__ __align__(16) __half g_QKVb[NROWS*1536];   // self QKV
__device__ __align__(16) __half g_QKVc[NROWS*1536];   // cross QKV
__device__ __align__(16) __half g_OH  [NROWS*Ee];
__device__ __align__(16) __half g_X1H [NROWS*Ee];
__device__ __align__(16) __half g_X2H [NROWS*Ee];
__device__ __align__(16) __half g_HfH [NROWS*Ff];
__device__ __align__(16) __half g_WcS [1536*Ee];
__device__ __align__(16) __half g_WoS [Ee*Ee];
__device__ __align__(16) __half g_WcQ [Ee*Ee];
__device__ __align__(16) __half g_WcKV[1024*Ee];
__device__ __align__(16) __half g_WoC [Ee*Ee];
__device__ __align__(16) __half g_W1H [Ee*Ff];
__device__ __align__(16) __half g_W2H [Ff*Ee];

// ================= PTX helpers =================
__device__ __forceinline__ uint32_t smem_u32(const void* p) {
    uint32_t a;
    asm("{ .reg .u64 t; cvta.to.shared.u64 t, %1; cvt.u32.u64 %0, t; }" : "=r"(a) : "l"(p));
    return a;
}
#define LDSM4(r, addr) \
    asm volatile("ldmatrix.sync.aligned.m8n8.x4.shared.b16 {%0,%1,%2,%3}, [%4];" \
        : "=r"((r)[0]), "=r"((r)[1]), "=r"((r)[2]), "=r"((r)[3]) : "r"(addr))
#define LDSM4T(r, addr) \
    asm volatile("ldmatrix.sync.aligned.m8n8.x4.trans.shared.b16 {%0,%1,%2,%3}, [%4];" \
        : "=r"((r)[0]), "=r"((r)[1]), "=r"((r)[2]), "=r"((r)[3]) : "r"(addr))
#define LDSM2(r, addr) \
    asm volatile("ldmatrix.sync.aligned.m8n8.x2.shared.b16 {%0,%1}, [%2];" \
        : "=r"((r)[0]), "=r"((r)[1]) : "r"(addr))
#define MMA_F16(d, a, b) \
    asm volatile("mma.sync.aligned.m16n8k16.row.col.f32.f16.f16.f32 " \
        "{%0,%1,%2,%3}, {%4,%5,%6,%7}, {%8,%9}, {%0,%1,%2,%3};" \
        : "+f"((d)[0]), "+f"((d)[1]), "+f"((d)[2]), "+f"((d)[3]) \
        : "r"((a)[0]), "r"((a)[1]), "r"((a)[2]), "r"((a)[3]), "r"((b)[0]), "r"((b)[1]))
#define CP_ASYNC16(dst, src) \
    asm volatile("cp.async.cg.shared.global [%0], [%1], 16;" :: "r"(dst), "l"(src))
#define CP_COMMIT() asm volatile("cp.async.commit_group;" ::: "memory")
#define CP_WAIT(n)  asm volatile("cp.async.wait_group %0;" :: "n"(n) : "memory")
__device__ __forceinline__ uint32_t pack_f16x2(float hi, float lo) {
    __half2 h = __floats2half2_rn(lo, hi);
    return *(uint32_t*)&h;
}

// ================= conversion helpers =================
__device__ __forceinline__ void conv_weight_tile(const float* src, __half* dh,
                                                 int K, int N, int t)
{
    int tn = N >> 5;
    int n0 = (t % tn) * 32, k0 = (t / tn) * 32;
    __shared__ float tile[32][33];
    int tx = threadIdx.x & 31, ty = threadIdx.x >> 5;
    for (int r = ty; r < 32; r += 8)
        tile[r][tx] = src[(size_t)(k0 + r) * N + n0 + tx];
    __syncthreads();
    for (int r = ty; r < 32; r += 8)
        dh[(size_t)(n0 + r) * K + k0 + tx] = __float2half_rn(tile[tx][r]);
}

// critical path: sWq/k/v + self biases + tgt
__global__ __launch_bounds__(256)
void conv_main(const float* sWq, const float* sWk, const float* sWv,
               const float* sbq, const float* sbk, const float* sbv,
               const float* tgt)
{
    int bid = blockIdx.x;
    if (bid < 768) {
        int rg = bid >> 8, t = bid & 255;
        const float* src = rg == 0 ? sWq : (rg == 1 ? sWk : sWv);
        conv_weight_tile(src, g_WcS + (size_t)rg * 512 * 512, 512, 512, t);
        return;
    }
    if (bid < 774) {
        int idx = (bid - 768) * 256 + threadIdx.x;
        const float* s = idx < 512 ? sbq : (idx < 1024 ? sbk : sbv);
        g_BcatS[idx] = s[idx & 511];
        return;
    }
    int i = (bid - 774) * 256 + threadIdx.x;
    float4 v = ((const float4*)tgt)[i];
    ((uint2*)g_TH)[i] = make_uint2(pack_f16x2(v.y, v.x), pack_f16x2(v.w, v.z));
}

// aux stream: cWk/cWv, sWo/cWq/cWo, FFN weights, cross biases, mem
__global__ __launch_bounds__(256)
void conv_aux(const float* cWk, const float* cWv,
              const float* sWo, const float* cWq, const float* cWo,
              const float* fW1, const float* fW2,
              const float* cbk, const float* cbv, const float* mem)
{
    int bid = blockIdx.x;
    if (bid < 512) {
        int rg = bid >> 8, t = bid & 255;
        conv_weight_tile(rg ? cWv : cWk, rg ? g_WcKV + 512*512 : g_WcKV, 512, 512, t);
        return;
    }
    if (bid < 768)  { conv_weight_tile(sWo, g_WoS, 512, 512, bid - 512);  return; }
    if (bid < 1024) { conv_weight_tile(cWq, g_WcQ, 512, 512, bid - 768);  return; }
    if (bid < 1280) { conv_weight_tile(cWo, g_WoC, 512, 512, bid - 1024); return; }
    if (bid < 2304) { conv_weight_tile(fW1, g_W1H, 512, 2048, bid - 1280); return; }
    if (bid < 3328) { conv_weight_tile(fW2, g_W2H, 2048, 512, bid - 2304); return; }
    if (bid < 3332) {
        int idx = (bid - 3328) * 256 + threadIdx.x;
        g_BcatC[idx] = (idx < 512 ? cbk : cbv)[idx & 511];
        return;
    }
    int i = (bid - 3332) * 256 + threadIdx.x;
    float4 v = ((const float4*)mem)[i];
    ((uint2*)g_MH)[i] = make_uint2(pack_f16x2(v.y, v.x), pack_f16x2(v.w, v.z));
}

// ================= cp.async pipelined HMMA GEMM (fp16, single-term) ========
// OMODE: 0 = fp32 out, 1 = fp16 out. MINB: min blocks/SM (register budget hint).
#define ROWB 80

template<int OMODE, int RELU, int BM, int STAGES>
__global__ __launch_bounds__(256, 3)
void gemm_pipe(const __half* __restrict__ Ah, const __half* __restrict__ Bh,
               const float* __restrict__ bias, float* __restrict__ C32,
               __half* __restrict__ C16h,
               int N, int K, int ldc)
{
    constexpr uint32_t AREG = (uint32_t)BM * ROWB;
    constexpr uint32_t BREG = 128u * ROWB;
    constexpr uint32_t STG = AREG + BREG;
    constexpr int MT = BM / 32;
    constexpr int WG = STAGES - 2;
    extern __shared__ char sm[];
    const uint32_t sb = smem_u32(sm);
    const int tid = threadIdx.x, lane = tid & 31, wid = tid >> 5;
    const int wm = wid >> 2, wn = wid & 3;
    const int m0 = blockIdx.y * BM, n0 = blockIdx.x * 128;

    const int l16 = lane & 15;
    const uint32_t a_lsm = sb +
        (uint32_t)((wm*(BM/2) + (lane & 7) + ((lane >> 3) & 1)*8) * ROWB + (lane >> 4)*16);
    const uint32_t b_lsm = sb + AREG +
        (uint32_t)((wn*32 + (l16 & 7)) * ROWB + (l16 >> 3)*16);

    float acc[MT][4][4];
    #pragma unroll
    for (int i = 0; i < MT; ++i)
        #pragma unroll
        for (int j = 0; j < 4; ++j) {
            acc[i][j][0] = 0.f; acc[i][j][1] = 0.f;
            acc[i][j][2] = 0.f; acc[i][j][3] = 0.f;
        }

    auto LDGA = [&](int kc, int st) {
        uint32_t base = (uint32_t)st * STG;
        #pragma unroll
        for (int i = 0; i < BM/64; ++i) {
            int c = tid + i*256; int row = c >> 2, k8 = c & 3;
            size_t g = (size_t)(m0 + row)*K + (size_t)kc*32 + k8*8;
            CP_ASYNC16(sb + base + row*ROWB + k8*16, Ah + g);
        }
        #pragma unroll
        for (int i = 0; i < 2; ++i) {
            int c = tid + i*256; int row = c >> 2, k8 = c & 3;
            size_t g = (size_t)(n0 + row)*K + (size_t)kc*32 + k8*8;
            CP_ASYNC16(sb + base + AREG + row*ROWB + k8*16, Bh + g);
        }
    };
    auto COMPUTE = [&](int st) {
        const uint32_t bo = (uint32_t)st * STG;
        #pragma unroll
        for (int k16 = 0; k16 < 2; ++k16) {
            uint32_t bh[4][2];
            #pragma unroll
            for (int nt = 0; nt < 4; ++nt)
                LDSM2(bh[nt], b_lsm + bo + nt*8*ROWB + k16*32);
            #pragma unroll
            for (int mt = 0; mt < MT; ++mt) {
                uint32_t ah[4];
                LDSM4(ah, a_lsm + bo + mt*16*ROWB + k16*32);
                #pragma unroll
                for (int nt = 0; nt < 4; ++nt)
                    MMA_F16(acc[mt][nt], ah, bh[nt]);
            }
        }
    };

    const int nk = K / 32;
    #pragma unroll
    for (int s = 0; s < STAGES - 1; ++s) {
        if (s < nk) LDGA(s, s);
        CP_COMMIT();
    }
    for (int kc = 0; kc < nk; ++kc) {
        CP_WAIT(WG);
        __syncthreads();
        int ns = kc + STAGES - 1;
        if (ns < nk) LDGA(ns, ns % STAGES);
        CP_COMMIT();
        COMPUTE(kc % STAGES);
    }

    const int gr = lane >> 2, qc = (lane & 3) * 2;
    #pragma unroll
    for (int mt = 0; mt < MT; ++mt) {
        #pragma unroll
        for (int nt = 0; nt < 4; ++nt) {
            int row = m0 + wm*(BM/2) + mt*16 + gr;
            int col = n0 + wn*32 + nt*8 + qc;
            float2 bv = *(const float2*)&bias[col];
            float v0 = acc[mt][nt][0] + bv.x, v1 = acc[mt][nt][1] + bv.y;
            float v2 = acc[mt][nt][2] + bv.x, v3 = acc[mt][nt][3] + bv.y;
            if (RELU) {
                v0 = fmaxf(v0, 0.f); v1 = fmaxf(v1, 0.f);
                v2 = fmaxf(v2, 0.f); v3 = fmaxf(v3, 0.f);
            }
            size_t o0 = (size_t)row * ldc + col;
            size_t o1 = (size_t)(row + 8) * ldc + col;
            if (OMODE == 0) {
                *(float2*)&C32[o0] = make_float2(v0, v1);
                *(float2*)&C32[o1] = make_float2(v2, v3);
            } else {
                *(uint32_t*)(C16h + o0) = pack_f16x2(v1, v0);
                *(uint32_t*)(C16h + o1) = pack_f16x2(v3, v2);
            }
        }
    }
}

// ========== HMMA flash attention (128 thr, 64 q-rows, unshifted softmax) ====
__global__ __launch_bounds__(128)
void attn_mma(const __half* __restrict__ QKV, __half* __restrict__ Oh)
{
    extern __shared__ char sm[];
    const int b = blockIdx.z, h = blockIdx.y, q0 = blockIdx.x * 64;
    const int tid = threadIdx.x, lane = tid & 31, wid = tid >> 5;
    const uint32_t sb = smem_u32(sm);

    #pragma unroll
    for (int i = 0; i < 4; ++i) {
        int c = tid + i*128; int row = c >> 3, ch = c & 7;
        CP_ASYNC16(sb + row*144 + ch*16,
                   QKV + (size_t)(b*Tt + q0 + row)*1536 + h*Dd + ch*8);
    }
    auto LDKV = [&](int blk, int st) {
        uint32_t base = 9216u + (uint32_t)st * 18432u;
        #pragma unroll
        for (int i = 0; i < 4; ++i) {
            int c = tid + i*128; int row = c >> 3, ch = c & 7;
            size_t g = (size_t)(b*Tt + blk*64 + row)*1536 + h*Dd + ch*8;
            CP_ASYNC16(sb + base + row*144 + ch*16,        QKV + g + 512);
            CP_ASYNC16(sb + base + 9216 + row*144 + ch*16, QKV + g + 1024);
        }
    };
    LDKV(0, 0);
    CP_COMMIT();

    uint32_t qf[4][4];
    float oa[8][4];
    #pragma unroll
    for (int f = 0; f < 8; ++f) { oa[f][0]=0.f; oa[f][1]=0.f; oa[f][2]=0.f; oa[f][3]=0.f; }
    float lA = 0.f, lB = 0.f;
    const float Cc = SCALE * 1.4426950408889634f;

    for (int blk = 0; blk < 16; ++blk) {
        CP_WAIT(0);
        __syncthreads();
        if (blk == 0) {
            #pragma unroll
            for (int k16 = 0; k16 < 4; ++k16)
                LDSM4(qf[k16], sb + (uint32_t)((wid*16 + (lane & 7) + ((lane >> 3) & 1)*8)*144
                                               + (lane >> 4)*16 + k16*32));
        }
        if (blk < 15) { LDKV(blk + 1, (blk + 1) & 1); }
        CP_COMMIT();

        const uint32_t uK = sb + 9216u + (uint32_t)(blk & 1) * 18432u;
        const uint32_t uV = uK + 9216u;

        float sc[8][4];
        #pragma unroll
        for (int f = 0; f < 8; ++f) { sc[f][0]=0.f; sc[f][1]=0.f; sc[f][2]=0.f; sc[f][3]=0.f; }
        #pragma unroll
        for (int k16 = 0; k16 < 4; ++k16) {
            #pragma unroll
            for (int kf = 0; kf < 4; ++kf) {
                uint32_t kb[4];
                LDSM4(kb, uK + (uint32_t)((kf*16 + (lane & 7) + (lane >> 4)*8)*144
                                          + ((lane >> 3) & 1)*16 + k16*32));
                MMA_F16(sc[2*kf],     qf[k16], kb);
                MMA_F16(sc[2*kf + 1], qf[k16], kb + 2);
            }
        }

        uint32_t pf[4][4];
        #pragma unroll
        for (int f = 0; f < 8; ++f) {
            float p0 = exp2f(sc[f][0]*Cc), p1 = exp2f(sc[f][1]*Cc);
            float p2 = exp2f(sc[f][2]*Cc), p3 = exp2f(sc[f][3]*Cc);
            lA += p0 + p1; lB += p2 + p3;
            int j16 = f >> 1, hf = f & 1;
            pf[j16][hf*2 + 0] = pack_f16x2(p1, p0);
            pf[j16][hf*2 + 1] = pack_f16x2(p3, p2);
        }

        #pragma unroll
        for (int j16 = 0; j16 < 4; ++j16) {
            #pragma unroll
            for (int nfp = 0; nfp < 4; ++nfp) {
                uint32_t vb[4];
                LDSM4T(vb, uV + (uint32_t)((j16*16 + (lane & 7) + ((lane >> 3) & 1)*8)*144
                                           + nfp*32 + (lane >> 4)*16));
                MMA_F16(oa[2*nfp],     pf[j16], vb);
                MMA_F16(oa[2*nfp + 1], pf[j16], vb + 2);
            }
        }
    }

    lA += __shfl_xor_sync(0xffffffffu, lA, 1);
    lA += __shfl_xor_sync(0xffffffffu, lA, 2);
    lB += __shfl_xor_sync(0xffffffffu, lB, 1);
    lB += __shfl_xor_sync(0xffffffffu, lB, 2);

    float iA = 1.f / lA, iB = 1.f / lB;
    int ra = q0 + wid*16 + (lane >> 2);
    #pragma unroll
    for (int f = 0; f < 8; ++f) {
        int col = h*Dd + f*8 + (lane & 3)*2;
        *(uint32_t*)(Oh + (size_t)(b*Tt + ra)*Ee + col)     = pack_f16x2(oa[f][1]*iA, oa[f][0]*iA);
        *(uint32_t*)(Oh + (size_t)(b*Tt + ra + 8)*Ee + col) = pack_f16x2(oa[f][3]*iB, oa[f][2]*iB);
    }
}

// ================= residual + LayerNorm =================
template<int MODE>   // 0: f32 only, 1: + fp16
__global__ __launch_bounds__(128)
void ln_kernel(const float* __restrict__ y, const float* __restrict__ res,
               const float* __restrict__ g, const float* __restrict__ be,
               float* __restrict__ out, __half* __restrict__ outH)
{
    const int row = blockIdx.x;
    const int tid = threadIdx.x;

    float4 v = ((const float4*)(y   + (size_t)row*Ee))[tid];
    float4 r = ((const float4*)(res + (size_t)row*Ee))[tid];
    v.x += r.x; v.y += r.y; v.z += r.z; v.w += r.w;

    float s  = v.x + v.y + v.z + v.w;
    float sq = v.x*v.x + v.y*v.y + v.z*v.z + v.w*v.w;
    #pragma unroll
    for (int o = 16; o > 0; o >>= 1) {
        s  += __shfl_xor_sync(0xffffffffu, s,  o);
        sq += __shfl_xor_sync(0xffffffffu, sq, o);
    }
    __shared__ float ss[4], ssq[4];
    int w = tid >> 5;
    if ((tid & 31) == 0) { ss[w] = s; ssq[w] = sq; }
    __syncthreads();
    s  = ss[0] + ss[1] + ss[2] + ss[3];
    sq = ssq[0] + ssq[1] + ssq[2] + ssq[3];

    const float inv_n = 1.f / (float)Ee;
    float mu  = s * inv_n;
    float var = sq * inv_n - mu*mu;
    float rs  = rsqrtf(var + LN_EPS);

    float4 gg = ((const float4*)g )[tid];
    float4 bb = ((const float4*)be)[tid];
    float4 o;
    o.x = (v.x - mu)*rs*gg.x + bb.x;
    o.y = (v.y - mu)*rs*gg.y + bb.y;
    o.z = (v.z - mu)*rs*gg.z + bb.z;
    o.w = (v.w - mu)*rs*gg.w + bb.w;
    ((float4*)(out + (size_t)row*Ee))[tid] = o;

    if (MODE >= 1) {
        size_t idx = (size_t)row*Ee + tid*4;
        *(uint2*)(outH + idx) = make_uint2(pack_f16x2(o.y, o.x), pack_f16x2(o.w, o.z));
    }
}

// ================= host orchestration =================
extern "C" void kernel_launch(void* const* d_in, const int* in_sizes, int n_in,
                              void* d_out, int out_size)
{
    const float* in[28];
    for (int i = 0; i < 28 && i < n_in; ++i) in[i] = (const float*)d_in[i];

    const float *tgt = in[0], *mem = in[1];
    const float *sWq,*sbq,*sWk,*sbk,*sWv,*sbv,*sWo,*sbo;
    const float *cWq,*cbq,*cWk,*cbk,*cWv,*cbv,*cWo,*cbo;
    const float *fW1,*fb1,*fW2,*fb2,*g1,*be1,*g2,*be2,*g3,*be3;

    bool sig = (in_sizes[3] == Ee);
    if (sig) {
        sWq=in[2];  sbq=in[3];  sWk=in[4];  sbk=in[5];
        sWv=in[6];  sbv=in[7];  sWo=in[8];  sbo=in[9];
        cWq=in[10]; cbq=in[11]; cWk=in[12]; cbk=in[13];
        cWv=in[14]; cbv=in[15]; cWo=in[16]; cbo=in[17];
        fW1=in[18]; fb1=in[19]; fW2=in[20]; fb2=in[21];
        g1=in[22];  be1=in[23]; g2=in[24];  be2=in[25]; g3=in[26]; be3=in[27];
    } else {
        sWq=in[2];  sWk=in[3];  sWv=in[4];  sWo=in[5];
        cWq=in[6];  cWk=in[7];  cWv=in[8];  cWo=in[9];
        sbq=in[10]; sbk=in[11]; sbv=in[12]; sbo=in[13];
        cbq=in[14]; cbk=in[15]; cbv=in[16]; cbo=in[17];
        fW1=in[18]; fb1=in[19]; fW2=in[20]; fb2=in[21];
        g1=in[22];  g2=in[23];  g3=in[24];  be1=in[25]; be2=in[26]; be3=in[27];
    }

    float *Y,*X1,*X2,*BcatS,*BcatC;
    __half *TH,*MH,*QKVb,*QKVc,*OH,*X1H,*X2H,*HfH;
    __half *WcS,*WoS,*WcQ,*WcKV,*WoC,*W1H,*W2H;
    cudaGetSymbolAddress((void**)&Y,    g_Y);
    cudaGetSymbolAddress((void**)&X1,   g_X1);
    cudaGetSymbolAddress((void**)&X2,   g_X2);
    cudaGetSymbolAddress((void**)&BcatS,g_BcatS);
    cudaGetSymbolAddress((void**)&BcatC,g_BcatC);
    cudaGetSymbolAddress((void**)&TH,   g_TH);
    cudaGetSymbolAddress((void**)&MH,   g_MH);
    cudaGetSymbolAddress((void**)&QKVb, g_QKVb);
    cudaGetSymbolAddress((void**)&QKVc, g_QKVc);
    cudaGetSymbolAddress((void**)&OH,   g_OH);
    cudaGetSymbolAddress((void**)&X1H,  g_X1H);
    cudaGetSymbolAddress((void**)&X2H,  g_X2H);
    cudaGetSymbolAddress((void**)&HfH,  g_HfH);
    cudaGetSymbolAddress((void**)&WcS,  g_WcS);
    cudaGetSymbolAddress((void**)&WoS,  g_WoS);
    cudaGetSymbolAddress((void**)&WcQ,  g_WcQ);
    cudaGetSymbolAddress((void**)&WcKV, g_WcKV);
    cudaGetSymbolAddress((void**)&WoC,  g_WoC);
    cudaGetSymbolAddress((void**)&W1H,  g_W1H);
    cudaGetSymbolAddress((void**)&W2H,  g_W2H);

    float* out = (float*)d_out;

    static cudaStream_t s2 = nullptr;
    static cudaEvent_t evF = nullptr, evA = nullptr, evJ = nullptr;
    if (!s2) {
        cudaStreamCreateWithFlags(&s2, cudaStreamNonBlocking);
        cudaEventCreateWithFlags(&evF, cudaEventDisableTiming);
        cudaEventCreateWithFlags(&evA, cudaEventDisableTiming);
        cudaEventCreateWithFlags(&evJ, cudaEventDisableTiming);
    }

    const int SM_G1 = 3 * ((128+128)*ROWB);     // BM128 S3: 61440 (3 blocks/SM)
    const int SM_G2 = 3 * (( 64+128)*ROWB);     // BM64  S3: 46080 (3+ blocks/SM)
    const int SM_AT = 9216 + 2*18432;           // attention: 46080

    cudaFuncSetAttribute(gemm_pipe<1,0,128,3>, cudaFuncAttributeMaxDynamicSharedMemorySize, SM_G1);
    cudaFuncSetAttribute(gemm_pipe<1,1,128,3>, cudaFuncAttributeMaxDynamicSharedMemorySize, SM_G1);
    cudaFuncSetAttribute(gemm_pipe<1,0, 64,3>, cudaFuncAttributeMaxDynamicSharedMemorySize, SM_G2);
    cudaFuncSetAttribute(gemm_pipe<0,0, 64,3>, cudaFuncAttributeMaxDynamicSharedMemorySize, SM_G2);
    cudaFuncSetAttribute(attn_mma, cudaFuncAttributeMaxDynamicSharedMemorySize, SM_AT);

    const dim3 gAttn(Tt/64, Hh, Bb);   // 512 blocks

    // ---- fork: aux conversions + cross-KV GEMM on s2 ----
    cudaEventRecord(evF, 0);
    cudaStreamWaitEvent(s2, evF, 0);
    conv_aux<<<5380, 256, 0, s2>>>(cWk, cWv, sWo, cWq, cWo, fW1, fW2, cbk, cbv, mem);
    cudaEventRecord(evA, s2);
    gemm_pipe<1,0,128,3><<<dim3(8,32), 256, SM_G1, s2>>>(MH, WcKV, BcatC, 0, QKVc+512, 1024, Ee, 1536);
    cudaEventRecord(evJ, s2);

    // ---- main chain: self-attention block ----
    conv_main<<<2822, 256>>>(sWq, sWk, sWv, sbq, sbk, sbv, tgt);
    gemm_pipe<1,0,128,3><<<dim3(12,32), 256, SM_G1>>>(TH, WcS, BcatS, 0, QKVb, 1536, Ee, 1536);
    attn_mma<<<gAttn, 128, SM_AT>>>(QKVb, OH);
    cudaStreamWaitEvent(0, evA, 0);   // WoS/WcQ/WoC/FFN weights ready
    gemm_pipe<0,0,64,3><<<dim3(4,64), 256, SM_G2>>>(OH, WoS, sbo, Y, 0, Ee, Ee, Ee);
    ln_kernel<1><<<NROWS, 128>>>(Y, tgt, g1, be1, X1, X1H);

    // ---- cross-attention block ----
    gemm_pipe<1,0,64,3><<<dim3(4,64), 256, SM_G2>>>(X1H, WcQ, cbq, 0, QKVc, Ee, Ee, 1536);
    cudaStreamWaitEvent(0, evJ, 0);
    attn_mma<<<gAttn, 128, SM_AT>>>(QKVc, OH);
    gemm_pipe<0,0,64,3><<<dim3(4,64), 256, SM_G2>>>(OH, WoC, cbo, Y, 0, Ee, Ee, Ee);
    ln_kernel<1><<<NROWS, 128>>>(Y, X1, g2, be2, X2, X2H);

    // ---- FFN block (single-term fp16) ----
    gemm_pipe<1,1,128,3><<<dim3(16,32), 256, SM_G1>>>(X2H, W1H, fb1, 0, HfH, Ff, Ee, Ff);
    gemm_pipe<0,0,64,3><<<dim3(4,64), 256, SM_G2>>>(HfH, W2H, fb2, Y, 0, Ee, Ff, Ee);
    ln_kernel<0><<<NROWS, 128>>>(Y, X2, g3, be3, out, 0);
}

// round 12
// speedup vs baseline: 1.2769x; 1.2769x over previous
#include <cuda_runtime.h>
#include <cuda_fp16.h>
#include <cstdint>
#include <math.h>

#define Bb 4
#define Tt 1024
#define Ee 512
#define Hh 8
#define Dd 64
#define Ff 2048
#define NROWS (Bb*Tt)
#define SCALE 0.125f
#define LN_EPS 1e-5f

// ================= device scratch (all 16-bit buffers are fp16) ===========
__device__ __align__(16) float g_Y [NROWS*Ee];
__device__ __align__(16) float g_X1[NROWS*Ee];
__device__ __align__(16) float g_X2[NROWS*Ee];
__device__ __align__(16) float g_BcatS[1536];
__device__ __align__(16) float g_BcatC[1024];
__device__ __align__(16) __half g_TH  [NROWS*Ee];
__device__ __align__(16) __half g_MH  [NROWS*Ee];
__device__ __align__(16) __half g_QKVb[NROWS*1536];   // self QKV
__device__ __align__(16) __half g_QKVc[NROWS*1536];   // cross QKV
__device__ __align__(16) __half g_OH  [NROWS*Ee];
__device__ __align__(16) __half g_X1H [NROWS*Ee];
__device__ __align__(16) __half g_X2H [NROWS*Ee];
__device__ __align__(16) __half g_HfH [NROWS*Ff];
__device__ __align__(16) __half g_WcS [1536*Ee];
__device__ __align__(16) __half g_WoS [Ee*Ee];
__device__ __align__(16) __half g_WcQ [Ee*Ee];
__device__ __align__(16) __half g_WcKV[1024*Ee];
__device__ __align__(16) __half g_WoC [Ee*Ee];
__device__ __align__(16) __half g_W1H [Ee*Ff];
__device__ __align__(16) __half g_W2H [Ff*Ee];

// ================= PTX helpers =================
__device__ __forceinline__ uint32_t smem_u32(const void* p) {
    uint32_t a;
    asm("{ .reg .u64 t; cvta.to.shared.u64 t, %1; cvt.u32.u64 %0, t; }" : "=r"(a) : "l"(p));
    return a;
}
#define LDSM4(r, addr) \
    asm volatile("ldmatrix.sync.aligned.m8n8.x4.shared.b16 {%0,%1,%2,%3}, [%4];" \
        : "=r"((r)[0]), "=r"((r)[1]), "=r"((r)[2]), "=r"((r)[3]) : "r"(addr))
#define LDSM4T(r, addr) \
    asm volatile("ldmatrix.sync.aligned.m8n8.x4.trans.shared.b16 {%0,%1,%2,%3}, [%4];" \
        : "=r"((r)[0]), "=r"((r)[1]), "=r"((r)[2]), "=r"((r)[3]) : "r"(addr))
#define LDSM2(r, addr) \
    asm volatile("ldmatrix.sync.aligned.m8n8.x2.shared.b16 {%0,%1}, [%2];" \
        : "=r"((r)[0]), "=r"((r)[1]) : "r"(addr))
#define MMA_F16(d, a, b) \
    asm volatile("mma.sync.aligned.m16n8k16.row.col.f32.f16.f16.f32 " \
        "{%0,%1,%2,%3}, {%4,%5,%6,%7}, {%8,%9}, {%0,%1,%2,%3};" \
        : "+f"((d)[0]), "+f"((d)[1]), "+f"((d)[2]), "+f"((d)[3]) \
        : "r"((a)[0]), "r"((a)[1]), "r"((a)[2]), "r"((a)[3]), "r"((b)[0]), "r"((b)[1]))
#define CP_ASYNC16(dst, src) \
    asm volatile("cp.async.cg.shared.global [%0], [%1], 16;" :: "r"(dst), "l"(src))
#define CP_COMMIT() asm volatile("cp.async.commit_group;" ::: "memory")
#define CP_WAIT(n)  asm volatile("cp.async.wait_group %0;" :: "n"(n) : "memory")
__device__ __forceinline__ uint32_t pack_f16x2(float hi, float lo) {
    __half2 h = __floats2half2_rn(lo, hi);
    return *(uint32_t*)&h;
}

// ================= conversion helpers =================
__device__ __forceinline__ void conv_weight_tile(const float* src, __half* dh,
                                                 int K, int N, int t)
{
    int tn = N >> 5;
    int n0 = (t % tn) * 32, k0 = (t / tn) * 32;
    __shared__ float tile[32][33];
    int tx = threadIdx.x & 31, ty = threadIdx.x >> 5;
    for (int r = ty; r < 32; r += 8)
        tile[r][tx] = src[(size_t)(k0 + r) * N + n0 + tx];
    __syncthreads();
    for (int r = ty; r < 32; r += 8)
        dh[(size_t)(n0 + r) * K + k0 + tx] = __float2half_rn(tile[tx][r]);
}

// critical path: sWq/k/v + self biases + tgt
__global__ __launch_bounds__(256)
void conv_main(const float* sWq, const float* sWk, const float* sWv,
               const float* sbq, const float* sbk, const float* sbv,
               const float* tgt)
{
    int bid = blockIdx.x;
    if (bid < 768) {
        int rg = bid >> 8, t = bid & 255;
        const float* src = rg == 0 ? sWq : (rg == 1 ? sWk : sWv);
        conv_weight_tile(src, g_WcS + (size_t)rg * 512 * 512, 512, 512, t);
        return;
    }
    if (bid < 774) {
        int idx = (bid - 768) * 256 + threadIdx.x;
        const float* s = idx < 512 ? sbq : (idx < 1024 ? sbk : sbv);
        g_BcatS[idx] = s[idx & 511];
        return;
    }
    int i = (bid - 774) * 256 + threadIdx.x;
    float4 v = ((const float4*)tgt)[i];
    ((uint2*)g_TH)[i] = make_uint2(pack_f16x2(v.y, v.x), pack_f16x2(v.w, v.z));
}

// aux stream: cWk/cWv, sWo/cWq/cWo, FFN weights, cross biases, mem
__global__ __launch_bounds__(256)
void conv_aux(const float* cWk, const float* cWv,
              const float* sWo, const float* cWq, const float* cWo,
              const float* fW1, const float* fW2,
              const float* cbk, const float* cbv, const float* mem)
{
    int bid = blockIdx.x;
    if (bid < 512) {
        int rg = bid >> 8, t = bid & 255;
        conv_weight_tile(rg ? cWv : cWk, rg ? g_WcKV + 512*512 : g_WcKV, 512, 512, t);
        return;
    }
    if (bid < 768)  { conv_weight_tile(sWo, g_WoS, 512, 512, bid - 512);  return; }
    if (bid < 1024) { conv_weight_tile(cWq, g_WcQ, 512, 512, bid - 768);  return; }
    if (bid < 1280) { conv_weight_tile(cWo, g_WoC, 512, 512, bid - 1024); return; }
    if (bid < 2304) { conv_weight_tile(fW1, g_W1H, 512, 2048, bid - 1280); return; }
    if (bid < 3328) { conv_weight_tile(fW2, g_W2H, 2048, 512, bid - 2304); return; }
    if (bid < 3332) {
        int idx = (bid - 3328) * 256 + threadIdx.x;
        g_BcatC[idx] = (idx < 512 ? cbk : cbv)[idx & 511];
        return;
    }
    int i = (bid - 3332) * 256 + threadIdx.x;
    float4 v = ((const float4*)mem)[i];
    ((uint2*)g_MH)[i] = make_uint2(pack_f16x2(v.y, v.x), pack_f16x2(v.w, v.z));
}

// ================= cp.async pipelined HMMA GEMM (fp16, single-term) ========
// OMODE: 0 = fp32 out, 1 = fp16 out. BK = K-slab (32 or 64).
// Row pad: BK32 -> 80 bytes, BK64 -> 144 bytes (both ldmatrix conflict-free).

template<int OMODE, int RELU, int BM, int BK, int STAGES>
__global__ __launch_bounds__(256)
void gemm_pipe(const __half* __restrict__ Ah, const __half* __restrict__ Bh,
               const float* __restrict__ bias, float* __restrict__ C32,
               __half* __restrict__ C16h,
               int N, int K, int ldc)
{
    constexpr uint32_t ROWBK = (BK == 32) ? 80u : 144u;
    constexpr int CH = BK / 8;                 // 16B chunks per row
    constexpr int K16 = BK / 16;               // k16 iterations per slab
    constexpr uint32_t AREG = (uint32_t)BM * ROWBK;
    constexpr uint32_t BREG = 128u * ROWBK;
    constexpr uint32_t STG = AREG + BREG;
    constexpr int MT = BM / 32;
    constexpr int WG = STAGES - 2;
    extern __shared__ char sm[];
    const uint32_t sb = smem_u32(sm);
    const int tid = threadIdx.x, lane = tid & 31, wid = tid >> 5;
    const int wm = wid >> 2, wn = wid & 3;
    const int m0 = blockIdx.y * BM, n0 = blockIdx.x * 128;

    const int l16 = lane & 15;
    const uint32_t a_lsm = sb +
        (uint32_t)((wm*(BM/2) + (lane & 7) + ((lane >> 3) & 1)*8) * ROWBK + (lane >> 4)*16);
    const uint32_t b_lsm = sb + AREG +
        (uint32_t)((wn*32 + (l16 & 7)) * ROWBK + (l16 >> 3)*16);

    float acc[MT][4][4];
    #pragma unroll
    for (int i = 0; i < MT; ++i)
        #pragma unroll
        for (int j = 0; j < 4; ++j) {
            acc[i][j][0] = 0.f; acc[i][j][1] = 0.f;
            acc[i][j][2] = 0.f; acc[i][j][3] = 0.f;
        }

    auto LDGA = [&](int kc, int st) {
        uint32_t base = (uint32_t)st * STG;
        #pragma unroll
        for (int i = 0; i < BM*CH/256; ++i) {
            int c = tid + i*256; int row = c / CH, k8 = c % CH;
            size_t g = (size_t)(m0 + row)*K + (size_t)kc*BK + k8*8;
            CP_ASYNC16(sb + base + row*ROWBK + k8*16, Ah + g);
        }
        #pragma unroll
        for (int i = 0; i < 128*CH/256; ++i) {
            int c = tid + i*256; int row = c / CH, k8 = c % CH;
            size_t g = (size_t)(n0 + row)*K + (size_t)kc*BK + k8*8;
            CP_ASYNC16(sb + base + AREG + row*ROWBK + k8*16, Bh + g);
        }
    };
    auto COMPUTE = [&](int st) {
        const uint32_t bo = (uint32_t)st * STG;
        #pragma unroll
        for (int k16 = 0; k16 < K16; ++k16) {
            uint32_t bh[4][2];
            #pragma unroll
            for (int nt = 0; nt < 4; ++nt)
                LDSM2(bh[nt], b_lsm + bo + nt*8*ROWBK + k16*32);
            #pragma unroll
            for (int mt = 0; mt < MT; ++mt) {
                uint32_t ah[4];
                LDSM4(ah, a_lsm + bo + mt*16*ROWBK + k16*32);
                #pragma unroll
                for (int nt = 0; nt < 4; ++nt)
                    MMA_F16(acc[mt][nt], ah, bh[nt]);
            }
        }
    };

    const int nk = K / BK;
    #pragma unroll
    for (int s = 0; s < STAGES - 1; ++s) {
        if (s < nk) LDGA(s, s);
        CP_COMMIT();
    }
    for (int kc = 0; kc < nk; ++kc) {
        CP_WAIT(WG);
        __syncthreads();
        int ns = kc + STAGES - 1;
        if (ns < nk) LDGA(ns, ns % STAGES);
        CP_COMMIT();
        COMPUTE(kc % STAGES);
    }

    const int gr = lane >> 2, qc = (lane & 3) * 2;
    #pragma unroll
    for (int mt = 0; mt < MT; ++mt) {
        #pragma unroll
        for (int nt = 0; nt < 4; ++nt) {
            int row = m0 + wm*(BM/2) + mt*16 + gr;
            int col = n0 + wn*32 + nt*8 + qc;
            float2 bv = *(const float2*)&bias[col];
            float v0 = acc[mt][nt][0] + bv.x, v1 = acc[mt][nt][1] + bv.y;
            float v2 = acc[mt][nt][2] + bv.x, v3 = acc[mt][nt][3] + bv.y;
            if (RELU) {
                v0 = fmaxf(v0, 0.f); v1 = fmaxf(v1, 0.f);
                v2 = fmaxf(v2, 0.f); v3 = fmaxf(v3, 0.f);
            }
            size_t o0 = (size_t)row * ldc + col;
            size_t o1 = (size_t)(row + 8) * ldc + col;
            if (OMODE == 0) {
                *(float2*)&C32[o0] = make_float2(v0, v1);
                *(float2*)&C32[o1] = make_float2(v2, v3);
            } else {
                *(uint32_t*)(C16h + o0) = pack_f16x2(v1, v0);
                *(uint32_t*)(C16h + o1) = pack_f16x2(v3, v2);
            }
        }
    }
}

// ========== HMMA flash attention (128 thr, 64 q-rows, unshifted softmax) ====
__global__ __launch_bounds__(128)
void attn_mma(const __half* __restrict__ QKV, __half* __restrict__ Oh)
{
    extern __shared__ char sm[];
    const int b = blockIdx.z, h = blockIdx.y, q0 = blockIdx.x * 64;
    const int tid = threadIdx.x, lane = tid & 31, wid = tid >> 5;
    const uint32_t sb = smem_u32(sm);

    #pragma unroll
    for (int i = 0; i < 4; ++i) {
        int c = tid + i*128; int row = c >> 3, ch = c & 7;
        CP_ASYNC16(sb + row*144 + ch*16,
                   QKV + (size_t)(b*Tt + q0 + row)*1536 + h*Dd + ch*8);
    }
    auto LDKV = [&](int blk, int st) {
        uint32_t base = 9216u + (uint32_t)st * 18432u;
        #pragma unroll
        for (int i = 0; i < 4; ++i) {
            int c = tid + i*128; int row = c >> 3, ch = c & 7;
            size_t g = (size_t)(b*Tt + blk*64 + row)*1536 + h*Dd + ch*8;
            CP_ASYNC16(sb + base + row*144 + ch*16,        QKV + g + 512);
            CP_ASYNC16(sb + base + 9216 + row*144 + ch*16, QKV + g + 1024);
        }
    };
    LDKV(0, 0);
    CP_COMMIT();

    uint32_t qf[4][4];
    float oa[8][4];
    #pragma unroll
    for (int f = 0; f < 8; ++f) { oa[f][0]=0.f; oa[f][1]=0.f; oa[f][2]=0.f; oa[f][3]=0.f; }
    float lA = 0.f, lB = 0.f;
    const float Cc = SCALE * 1.4426950408889634f;

    for (int blk = 0; blk < 16; ++blk) {
        CP_WAIT(0);
        __syncthreads();
        if (blk == 0) {
            #pragma unroll
            for (int k16 = 0; k16 < 4; ++k16)
                LDSM4(qf[k16], sb + (uint32_t)((wid*16 + (lane & 7) + ((lane >> 3) & 1)*8)*144
                                               + (lane >> 4)*16 + k16*32));
        }
        if (blk < 15) { LDKV(blk + 1, (blk + 1) & 1); }
        CP_COMMIT();

        const uint32_t uK = sb + 9216u + (uint32_t)(blk & 1) * 18432u;
        const uint32_t uV = uK + 9216u;

        float sc[8][4];
        #pragma unroll
        for (int f = 0; f < 8; ++f) { sc[f][0]=0.f; sc[f][1]=0.f; sc[f][2]=0.f; sc[f][3]=0.f; }
        #pragma unroll
        for (int k16 = 0; k16 < 4; ++k16) {
            #pragma unroll
            for (int kf = 0; kf < 4; ++kf) {
                uint32_t kb[4];
                LDSM4(kb, uK + (uint32_t)((kf*16 + (lane & 7) + (lane >> 4)*8)*144
                                          + ((lane >> 3) & 1)*16 + k16*32));
                MMA_F16(sc[2*kf],     qf[k16], kb);
                MMA_F16(sc[2*kf + 1], qf[k16], kb + 2);
            }
        }

        uint32_t pf[4][4];
        #pragma unroll
        for (int f = 0; f < 8; ++f) {
            float p0 = exp2f(sc[f][0]*Cc), p1 = exp2f(sc[f][1]*Cc);
            float p2 = exp2f(sc[f][2]*Cc), p3 = exp2f(sc[f][3]*Cc);
            lA += p0 + p1; lB += p2 + p3;
            int j16 = f >> 1, hf = f & 1;
            pf[j16][hf*2 + 0] = pack_f16x2(p1, p0);
            pf[j16][hf*2 + 1] = pack_f16x2(p3, p2);
        }

        #pragma unroll
        for (int j16 = 0; j16 < 4; ++j16) {
            #pragma unroll
            for (int nfp = 0; nfp < 4; ++nfp) {
                uint32_t vb[4];
                LDSM4T(vb, uV + (uint32_t)((j16*16 + (lane & 7) + ((lane >> 3) & 1)*8)*144
                                           + nfp*32 + (lane >> 4)*16));
                MMA_F16(oa[2*nfp],     pf[j16], vb);
                MMA_F16(oa[2*nfp + 1], pf[j16], vb + 2);
            }
        }
    }

    lA += __shfl_xor_sync(0xffffffffu, lA, 1);
    lA += __shfl_xor_sync(0xffffffffu, lA, 2);
    lB += __shfl_xor_sync(0xffffffffu, lB, 1);
    lB += __shfl_xor_sync(0xffffffffu, lB, 2);

    float iA = 1.f / lA, iB = 1.f / lB;
    int ra = q0 + wid*16 + (lane >> 2);
    #pragma unroll
    for (int f = 0; f < 8; ++f) {
        int col = h*Dd + f*8 + (lane & 3)*2;
        *(uint32_t*)(Oh + (size_t)(b*Tt + ra)*Ee + col)     = pack_f16x2(oa[f][1]*iA, oa[f][0]*iA);
        *(uint32_t*)(Oh + (size_t)(b*Tt + ra + 8)*Ee + col) = pack_f16x2(oa[f][3]*iB, oa[f][2]*iB);
    }
}

// ================= residual + LayerNorm =================
template<int MODE>   // 0: f32 only, 1: + fp16
__global__ __launch_bounds__(128)
void ln_kernel(const float* __restrict__ y, const float* __restrict__ res,
               const float* __restrict__ g, const float* __restrict__ be,
               float* __restrict__ out, __half* __restrict__ outH)
{
    const int row = blockIdx.x;
    const int tid = threadIdx.x;

    float4 v = ((const float4*)(y   + (size_t)row*Ee))[tid];
    float4 r = ((const float4*)(res + (size_t)row*Ee))[tid];
    v.x += r.x; v.y += r.y; v.z += r.z; v.w += r.w;

    float s  = v.x + v.y + v.z + v.w;
    float sq = v.x*v.x + v.y*v.y + v.z*v.z + v.w*v.w;
    #pragma unroll
    for (int o = 16; o > 0; o >>= 1) {
        s  += __shfl_xor_sync(0xffffffffu, s,  o);
        sq += __shfl_xor_sync(0xffffffffu, sq, o);
    }
    __shared__ float ss[4], ssq[4];
    int w = tid >> 5;
    if ((tid & 31) == 0) { ss[w] = s; ssq[w] = sq; }
    __syncthreads();
    s  = ss[0] + ss[1] + ss[2] + ss[3];
    sq = ssq[0] + ssq[1] + ssq[2] + ssq[3];

    const float inv_n = 1.f / (float)Ee;
    float mu  = s * inv_n;
    float var = sq * inv_n - mu*mu;
    float rs  = rsqrtf(var + LN_EPS);

    float4 gg = ((const float4*)g )[tid];
    float4 bb = ((const float4*)be)[tid];
    float4 o;
    o.x = (v.x - mu)*rs*gg.x + bb.x;
    o.y = (v.y - mu)*rs*gg.y + bb.y;
    o.z = (v.z - mu)*rs*gg.z + bb.z;
    o.w = (v.w - mu)*rs*gg.w + bb.w;
    ((float4*)(out + (size_t)row*Ee))[tid] = o;

    if (MODE >= 1) {
        size_t idx = (size_t)row*Ee + tid*4;
        *(uint2*)(outH + idx) = make_uint2(pack_f16x2(o.y, o.x), pack_f16x2(o.w, o.z));
    }
}

// ================= host orchestration =================
extern "C" void kernel_launch(void* const* d_in, const int* in_sizes, int n_in,
                              void* d_out, int out_size)
{
    const float* in[28];
    for (int i = 0; i < 28 && i < n_in; ++i) in[i] = (const float*)d_in[i];

    const float *tgt = in[0], *mem = in[1];
    const float *sWq,*sbq,*sWk,*sbk,*sWv,*sbv,*sWo,*sbo;
    const float *cWq,*cbq,*cWk,*cbk,*cWv,*cbv,*cWo,*cbo;
    const float *fW1,*fb1,*fW2,*fb2,*g1,*be1,*g2,*be2,*g3,*be3;

    bool sig = (in_sizes[3] == Ee);
    if (sig) {
        sWq=in[2];  sbq=in[3];  sWk=in[4];  sbk=in[5];
        sWv=in[6];  sbv=in[7];  sWo=in[8];  sbo=in[9];
        cWq=in[10]; cbq=in[11]; cWk=in[12]; cbk=in[13];
        cWv=in[14]; cbv=in[15]; cWo=in[16]; cbo=in[17];
        fW1=in[18]; fb1=in[19]; fW2=in[20]; fb2=in[21];
        g1=in[22];  be1=in[23]; g2=in[24];  be2=in[25]; g3=in[26]; be3=in[27];
    } else {
        sWq=in[2];  sWk=in[3];  sWv=in[4];  sWo=in[5];
        cWq=in[6];  cWk=in[7];  cWv=in[8];  cWo=in[9];
        sbq=in[10]; sbk=in[11]; sbv=in[12]; sbo=in[13];
        cbq=in[14]; cbk=in[15]; cbv=in[16]; cbo=in[17];
        fW1=in[18]; fb1=in[19]; fW2=in[20]; fb2=in[21];
        g1=in[22];  g2=in[23];  g3=in[24];  be1=in[25]; be2=in[26]; be3=in[27];
    }

    float *Y,*X1,*X2,*BcatS,*BcatC;
    __half *TH,*MH,*QKVb,*QKVc,*OH,*X1H,*X2H,*HfH;
    __half *WcS,*WoS,*WcQ,*WcKV,*WoC,*W1H,*W2H;
    cudaGetSymbolAddress((void**)&Y,    g_Y);
    cudaGetSymbolAddress((void**)&X1,   g_X1);
    cudaGetSymbolAddress((void**)&X2,   g_X2);
    cudaGetSymbolAddress((void**)&BcatS,g_BcatS);
    cudaGetSymbolAddress((void**)&BcatC,g_BcatC);
    cudaGetSymbolAddress((void**)&TH,   g_TH);
    cudaGetSymbolAddress((void**)&MH,   g_MH);
    cudaGetSymbolAddress((void**)&QKVb, g_QKVb);
    cudaGetSymbolAddress((void**)&QKVc, g_QKVc);
    cudaGetSymbolAddress((void**)&OH,   g_OH);
    cudaGetSymbolAddress((void**)&X1H,  g_X1H);
    cudaGetSymbolAddress((void**)&X2H,  g_X2H);
    cudaGetSymbolAddress((void**)&HfH,  g_HfH);
    cudaGetSymbolAddress((void**)&WcS,  g_WcS);
    cudaGetSymbolAddress((void**)&WoS,  g_WoS);
    cudaGetSymbolAddress((void**)&WcQ,  g_WcQ);
    cudaGetSymbolAddress((void**)&WcKV, g_WcKV);
    cudaGetSymbolAddress((void**)&WoC,  g_WoC);
    cudaGetSymbolAddress((void**)&W1H,  g_W1H);
    cudaGetSymbolAddress((void**)&W2H,  g_W2H);

    float* out = (float*)d_out;

    static cudaStream_t s2 = nullptr;
    static cudaEvent_t evF = nullptr, evA = nullptr, evJ = nullptr;
    if (!s2) {
        cudaStreamCreateWithFlags(&s2, cudaStreamNonBlocking);
        cudaEventCreateWithFlags(&evF, cudaEventDisableTiming);
        cudaEventCreateWithFlags(&evA, cudaEventDisableTiming);
        cudaEventCreateWithFlags(&evJ, cudaEventDisableTiming);
    }

    const int SM_B64 = 3 * ((128+128)*144);     // BK64 BM128 S3: 110592
    const int SM_B32 = 4 * (( 64+128)*80);      // BK32 BM64  S4: 61440
    const int SM_AT  = 9216 + 2*18432;          // attention: 46080

    cudaFuncSetAttribute(gemm_pipe<1,0,128,64,3>, cudaFuncAttributeMaxDynamicSharedMemorySize, SM_B64);
    cudaFuncSetAttribute(gemm_pipe<1,1,128,64,3>, cudaFuncAttributeMaxDynamicSharedMemorySize, SM_B64);
    cudaFuncSetAttribute(gemm_pipe<1,0, 64,32,4>, cudaFuncAttributeMaxDynamicSharedMemorySize, SM_B32);
    cudaFuncSetAttribute(gemm_pipe<0,0, 64,32,4>, cudaFuncAttributeMaxDynamicSharedMemorySize, SM_B32);
    cudaFuncSetAttribute(attn_mma, cudaFuncAttributeMaxDynamicSharedMemorySize, SM_AT);

    const dim3 gAttn(Tt/64, Hh, Bb);   // 512 blocks

    // ---- fork: aux conversions + cross-KV GEMM on s2 ----
    cudaEventRecord(evF, 0);
    cudaStreamWaitEvent(s2, evF, 0);
    conv_aux<<<5380, 256, 0, s2>>>(cWk, cWv, sWo, cWq, cWo, fW1, fW2, cbk, cbv, mem);
    cudaEventRecord(evA, s2);
    gemm_pipe<1,0,128,64,3><<<dim3(8,32), 256, SM_B64, s2>>>(MH, WcKV, BcatC, 0, QKVc+512, 1024, Ee, 1536);
    cudaEventRecord(evJ, s2);

    // ---- main chain: self-attention block ----
    conv_main<<<2822, 256>>>(sWq, sWk, sWv, sbq, sbk, sbv, tgt);
    gemm_pipe<1,0,128,64,3><<<dim3(12,32), 256, SM_B64>>>(TH, WcS, BcatS, 0, QKVb, 1536, Ee, 1536);
    attn_mma<<<gAttn, 128, SM_AT>>>(QKVb, OH);
    cudaStreamWaitEvent(0, evA, 0);   // WoS/WcQ/WoC/FFN weights ready
    gemm_pipe<0,0,64,32,4><<<dim3(4,64), 256, SM_B32>>>(OH, WoS, sbo, Y, 0, Ee, Ee, Ee);
    ln_kernel<1><<<NROWS, 128>>>(Y, tgt, g1, be1, X1, X1H);

    // ---- cross-attention block ----
    gemm_pipe<1,0,64,32,4><<<dim3(4,64), 256, SM_B32>>>(X1H, WcQ, cbq, 0, QKVc, Ee, Ee, 1536);
    cudaStreamWaitEvent(0, evJ, 0);
    attn_mma<<<gAttn, 128, SM_AT>>>(QKVc, OH);
    gemm_pipe<0,0,64,32,4><<<dim3(4,64), 256, SM_B32>>>(OH, WoC, cbo, Y, 0, Ee, Ee, Ee);
    ln_kernel<1><<<NROWS, 128>>>(Y, X1, g2, be2, X2, X2H);

    // ---- FFN block (single-term fp16) ----
    gemm_pipe<1,1,128,64,3><<<dim3(16,32), 256, SM_B64>>>(X2H, W1H, fb1, 0, HfH, Ff, Ee, Ff);
    gemm_pipe<0,0,64,32,4><<<dim3(4,64), 256, SM_B32>>>(HfH, W2H, fb2, Y, 0, Ee, Ff, Ee);
    ln_kernel<0><<<NROWS, 128>>>(Y, X2, g3, be3, out, 0);
}

// round 13
// speedup vs baseline: 1.3046x; 1.0217x over previous
#include <cuda_runtime.h>
#include <cuda_fp16.h>
#include <cstdint>
#include <math.h>

#define Bb 4
#define Tt 1024
#define Ee 512
#define Hh 8
#define Dd 64
#define Ff 2048
#define NROWS (Bb*Tt)
#define SCALE 0.125f
#define LN_EPS 1e-5f

// ================= device scratch (all 16-bit buffers are fp16) ===========
__device__ __align__(16) float g_Y [NROWS*Ee];
__device__ __align__(16) float g_X1[NROWS*Ee];
__device__ __align__(16) float g_X2[NROWS*Ee];
__device__ __align__(16) float g_BcatS[1536];
__device__ __align__(16) float g_BcatC[1024];
__device__ __align__(16) __half g_TH  [NROWS*Ee];
__device__ __align__(16) __half g_MH  [NROWS*Ee];
__device__ __align__(16) __half g_QKVb[NROWS*1536];   // self QKV
__device__ __align__(16) __half g_QKVc[NROWS*1536];   // cross QKV
__device__ __align__(16) __half g_OH  [NROWS*Ee];
__device__ __align__(16) __half g_X1H [NROWS*Ee];
__device__ __align__(16) __half g_X2H [NROWS*Ee];
__device__ __align__(16) __half g_HfH [NROWS*Ff];
__device__ __align__(16) __half g_WcS [1536*Ee];
__device__ __align__(16) __half g_WoS [Ee*Ee];
__device__ __align__(16) __half g_WcQ [Ee*Ee];
__device__ __align__(16) __half g_WcKV[1024*Ee];
__device__ __align__(16) __half g_WoC [Ee*Ee];
__device__ __align__(16) __half g_W1H [Ee*Ff];
__device__ __align__(16) __half g_W2H [Ff*Ee];

// ================= PTX helpers =================
__device__ __forceinline__ uint32_t smem_u32(const void* p) {
    uint32_t a;
    asm("{ .reg .u64 t; cvta.to.shared.u64 t, %1; cvt.u32.u64 %0, t; }" : "=r"(a) : "l"(p));
    return a;
}
#define LDSM4(r, addr) \
    asm volatile("ldmatrix.sync.aligned.m8n8.x4.shared.b16 {%0,%1,%2,%3}, [%4];" \
        : "=r"((r)[0]), "=r"((r)[1]), "=r"((r)[2]), "=r"((r)[3]) : "r"(addr))
#define LDSM4T(r, addr) \
    asm volatile("ldmatrix.sync.aligned.m8n8.x4.trans.shared.b16 {%0,%1,%2,%3}, [%4];" \
        : "=r"((r)[0]), "=r"((r)[1]), "=r"((r)[2]), "=r"((r)[3]) : "r"(addr))
#define LDSM2(r, addr) \
    asm volatile("ldmatrix.sync.aligned.m8n8.x2.shared.b16 {%0,%1}, [%2];" \
        : "=r"((r)[0]), "=r"((r)[1]) : "r"(addr))
#define MMA_F16(d, a, b) \
    asm volatile("mma.sync.aligned.m16n8k16.row.col.f32.f16.f16.f32 " \
        "{%0,%1,%2,%3}, {%4,%5,%6,%7}, {%8,%9}, {%0,%1,%2,%3};" \
        : "+f"((d)[0]), "+f"((d)[1]), "+f"((d)[2]), "+f"((d)[3]) \
        : "r"((a)[0]), "r"((a)[1]), "r"((a)[2]), "r"((a)[3]), "r"((b)[0]), "r"((b)[1]))
#define CP_ASYNC16(dst, src) \
    asm volatile("cp.async.cg.shared.global [%0], [%1], 16;" :: "r"(dst), "l"(src))
#define CP_COMMIT() asm volatile("cp.async.commit_group;" ::: "memory")
#define CP_WAIT(n)  asm volatile("cp.async.wait_group %0;" :: "n"(n) : "memory")
__device__ __forceinline__ uint32_t pack_f16x2(float hi, float lo) {
    __half2 h = __floats2half2_rn(lo, hi);
    return *(uint32_t*)&h;
}

// ================= conversion helpers =================
__device__ __forceinline__ void conv_weight_tile(const float* src, __half* dh,
                                                 int K, int N, int t)
{
    int tn = N >> 5;
    int n0 = (t % tn) * 32, k0 = (t / tn) * 32;
    __shared__ float tile[32][33];
    int tx = threadIdx.x & 31, ty = threadIdx.x >> 5;
    for (int r = ty; r < 32; r += 8)
        tile[r][tx] = src[(size_t)(k0 + r) * N + n0 + tx];
    __syncthreads();
    for (int r = ty; r < 32; r += 8)
        dh[(size_t)(n0 + r) * K + k0 + tx] = __float2half_rn(tile[tx][r]);
}

// critical path: sWq/k/v + self biases + tgt
__global__ __launch_bounds__(256)
void conv_main(const float* sWq, const float* sWk, const float* sWv,
               const float* sbq, const float* sbk, const float* sbv,
               const float* tgt)
{
    int bid = blockIdx.x;
    if (bid < 768) {
        int rg = bid >> 8, t = bid & 255;
        const float* src = rg == 0 ? sWq : (rg == 1 ? sWk : sWv);
        conv_weight_tile(src, g_WcS + (size_t)rg * 512 * 512, 512, 512, t);
        return;
    }
    if (bid < 774) {
        int idx = (bid - 768) * 256 + threadIdx.x;
        const float* s = idx < 512 ? sbq : (idx < 1024 ? sbk : sbv);
        g_BcatS[idx] = s[idx & 511];
        return;
    }
    int i = (bid - 774) * 256 + threadIdx.x;
    float4 v = ((const float4*)tgt)[i];
    ((uint2*)g_TH)[i] = make_uint2(pack_f16x2(v.y, v.x), pack_f16x2(v.w, v.z));
}

// aux stream: cWk/cWv, sWo/cWq/cWo, FFN weights, cross biases, mem
__global__ __launch_bounds__(256)
void conv_aux(const float* cWk, const float* cWv,
              const float* sWo, const float* cWq, const float* cWo,
              const float* fW1, const float* fW2,
              const float* cbk, const float* cbv, const float* mem)
{
    int bid = blockIdx.x;
    if (bid < 512) {
        int rg = bid >> 8, t = bid & 255;
        conv_weight_tile(rg ? cWv : cWk, rg ? g_WcKV + 512*512 : g_WcKV, 512, 512, t);
        return;
    }
    if (bid < 768)  { conv_weight_tile(sWo, g_WoS, 512, 512, bid - 512);  return; }
    if (bid < 1024) { conv_weight_tile(cWq, g_WcQ, 512, 512, bid - 768);  return; }
    if (bid < 1280) { conv_weight_tile(cWo, g_WoC, 512, 512, bid - 1024); return; }
    if (bid < 2304) { conv_weight_tile(fW1, g_W1H, 512, 2048, bid - 1280); return; }
    if (bid < 3328) { conv_weight_tile(fW2, g_W2H, 2048, 512, bid - 2304); return; }
    if (bid < 3332) {
        int idx = (bid - 3328) * 256 + threadIdx.x;
        g_BcatC[idx] = (idx < 512 ? cbk : cbv)[idx & 511];
        return;
    }
    int i = (bid - 3332) * 256 + threadIdx.x;
    float4 v = ((const float4*)mem)[i];
    ((uint2*)g_MH)[i] = make_uint2(pack_f16x2(v.y, v.x), pack_f16x2(v.w, v.z));
}

// ================= cp.async pipelined HMMA GEMM (fp16, single-term) ========
// OMODE: 0 = fp32 out, 1 = fp16 out. BK = K-slab (32 or 64).
// Row pad: BK32 -> 80 bytes, BK64 -> 144 bytes (both ldmatrix conflict-free).

template<int OMODE, int RELU, int BM, int BK, int STAGES>
__global__ __launch_bounds__(256)
void gemm_pipe(const __half* __restrict__ Ah, const __half* __restrict__ Bh,
               const float* __restrict__ bias, float* __restrict__ C32,
               __half* __restrict__ C16h,
               int N, int K, int ldc)
{
    constexpr uint32_t ROWBK = (BK == 32) ? 80u : 144u;
    constexpr int CH = BK / 8;                 // 16B chunks per row
    constexpr int K16 = BK / 16;               // k16 iterations per slab
    constexpr uint32_t AREG = (uint32_t)BM * ROWBK;
    constexpr uint32_t BREG = 128u * ROWBK;
    constexpr uint32_t STG = AREG + BREG;
    constexpr int MT = BM / 32;
    constexpr int WG = STAGES - 2;
    extern __shared__ char sm[];
    const uint32_t sb = smem_u32(sm);
    const int tid = threadIdx.x, lane = tid & 31, wid = tid >> 5;
    const int wm = wid >> 2, wn = wid & 3;
    const int m0 = blockIdx.y * BM, n0 = blockIdx.x * 128;

    const int l16 = lane & 15;
    const uint32_t a_lsm = sb +
        (uint32_t)((wm*(BM/2) + (lane & 7) + ((lane >> 3) & 1)*8) * ROWBK + (lane >> 4)*16);
    const uint32_t b_lsm = sb + AREG +
        (uint32_t)((wn*32 + (l16 & 7)) * ROWBK + (l16 >> 3)*16);

    float acc[MT][4][4];
    #pragma unroll
    for (int i = 0; i < MT; ++i)
        #pragma unroll
        for (int j = 0; j < 4; ++j) {
            acc[i][j][0] = 0.f; acc[i][j][1] = 0.f;
            acc[i][j][2] = 0.f; acc[i][j][3] = 0.f;
        }

    auto LDGA = [&](int kc, int st) {
        uint32_t base = (uint32_t)st * STG;
        #pragma unroll
        for (int i = 0; i < BM*CH/256; ++i) {
            int c = tid + i*256; int row = c / CH, k8 = c % CH;
            size_t g = (size_t)(m0 + row)*K + (size_t)kc*BK + k8*8;
            CP_ASYNC16(sb + base + row*ROWBK + k8*16, Ah + g);
        }
        #pragma unroll
        for (int i = 0; i < 128*CH/256; ++i) {
            int c = tid + i*256; int row = c / CH, k8 = c % CH;
            size_t g = (size_t)(n0 + row)*K + (size_t)kc*BK + k8*8;
            CP_ASYNC16(sb + base + AREG + row*ROWBK + k8*16, Bh + g);
        }
    };
    auto COMPUTE = [&](int st) {
        const uint32_t bo = (uint32_t)st * STG;
        #pragma unroll
        for (int k16 = 0; k16 < K16; ++k16) {
            uint32_t bh[4][2];
            #pragma unroll
            for (int nt = 0; nt < 4; ++nt)
                LDSM2(bh[nt], b_lsm + bo + nt*8*ROWBK + k16*32);
            #pragma unroll
            for (int mt = 0; mt < MT; ++mt) {
                uint32_t ah[4];
                LDSM4(ah, a_lsm + bo + mt*16*ROWBK + k16*32);
                #pragma unroll
                for (int nt = 0; nt < 4; ++nt)
                    MMA_F16(acc[mt][nt], ah, bh[nt]);
            }
        }
    };

    const int nk = K / BK;
    #pragma unroll
    for (int s = 0; s < STAGES - 1; ++s) {
        if (s < nk) LDGA(s, s);
        CP_COMMIT();
    }
    for (int kc = 0; kc < nk; ++kc) {
        CP_WAIT(WG);
        __syncthreads();
        int ns = kc + STAGES - 1;
        if (ns < nk) LDGA(ns, ns % STAGES);
        CP_COMMIT();
        COMPUTE(kc % STAGES);
    }

    const int gr = lane >> 2, qc = (lane & 3) * 2;
    #pragma unroll
    for (int mt = 0; mt < MT; ++mt) {
        #pragma unroll
        for (int nt = 0; nt < 4; ++nt) {
            int row = m0 + wm*(BM/2) + mt*16 + gr;
            int col = n0 + wn*32 + nt*8 + qc;
            float2 bv = *(const float2*)&bias[col];
            float v0 = acc[mt][nt][0] + bv.x, v1 = acc[mt][nt][1] + bv.y;
            float v2 = acc[mt][nt][2] + bv.x, v3 = acc[mt][nt][3] + bv.y;
            if (RELU) {
                v0 = fmaxf(v0, 0.f); v1 = fmaxf(v1, 0.f);
                v2 = fmaxf(v2, 0.f); v3 = fmaxf(v3, 0.f);
            }
            size_t o0 = (size_t)row * ldc + col;
            size_t o1 = (size_t)(row + 8) * ldc + col;
            if (OMODE == 0) {
                *(float2*)&C32[o0] = make_float2(v0, v1);
                *(float2*)&C32[o1] = make_float2(v2, v3);
            } else {
                *(uint32_t*)(C16h + o0) = pack_f16x2(v1, v0);
                *(uint32_t*)(C16h + o1) = pack_f16x2(v3, v2);
            }
        }
    }
}

// ========== HMMA flash attention (128 thr, 64 q-rows, unshifted softmax) ====
__global__ __launch_bounds__(128)
void attn_mma(const __half* __restrict__ QKV, __half* __restrict__ Oh)
{
    extern __shared__ char sm[];
    const int b = blockIdx.z, h = blockIdx.y, q0 = blockIdx.x * 64;
    const int tid = threadIdx.x, lane = tid & 31, wid = tid >> 5;
    const uint32_t sb = smem_u32(sm);

    #pragma unroll
    for (int i = 0; i < 4; ++i) {
        int c = tid + i*128; int row = c >> 3, ch = c & 7;
        CP_ASYNC16(sb + row*144 + ch*16,
                   QKV + (size_t)(b*Tt + q0 + row)*1536 + h*Dd + ch*8);
    }
    auto LDKV = [&](int blk, int st) {
        uint32_t base = 9216u + (uint32_t)st * 18432u;
        #pragma unroll
        for (int i = 0; i < 4; ++i) {
            int c = tid + i*128; int row = c >> 3, ch = c & 7;
            size_t g = (size_t)(b*Tt + blk*64 + row)*1536 + h*Dd + ch*8;
            CP_ASYNC16(sb + base + row*144 + ch*16,        QKV + g + 512);
            CP_ASYNC16(sb + base + 9216 + row*144 + ch*16, QKV + g + 1024);
        }
    };
    LDKV(0, 0);
    CP_COMMIT();

    uint32_t qf[4][4];
    float oa[8][4];
    #pragma unroll
    for (int f = 0; f < 8; ++f) { oa[f][0]=0.f; oa[f][1]=0.f; oa[f][2]=0.f; oa[f][3]=0.f; }
    float lA = 0.f, lB = 0.f;
    const float Cc = SCALE * 1.4426950408889634f;

    for (int blk = 0; blk < 16; ++blk) {
        CP_WAIT(0);
        __syncthreads();
        if (blk == 0) {
            #pragma unroll
            for (int k16 = 0; k16 < 4; ++k16)
                LDSM4(qf[k16], sb + (uint32_t)((wid*16 + (lane & 7) + ((lane >> 3) & 1)*8)*144
                                               + (lane >> 4)*16 + k16*32));
        }
        if (blk < 15) { LDKV(blk + 1, (blk + 1) & 1); }
        CP_COMMIT();

        const uint32_t uK = sb + 9216u + (uint32_t)(blk & 1) * 18432u;
        const uint32_t uV = uK + 9216u;

        float sc[8][4];
        #pragma unroll
        for (int f = 0; f < 8; ++f) { sc[f][0]=0.f; sc[f][1]=0.f; sc[f][2]=0.f; sc[f][3]=0.f; }
        #pragma unroll
        for (int k16 = 0; k16 < 4; ++k16) {
            #pragma unroll
            for (int kf = 0; kf < 4; ++kf) {
                uint32_t kb[4];
                LDSM4(kb, uK + (uint32_t)((kf*16 + (lane & 7) + (lane >> 4)*8)*144
                                          + ((lane >> 3) & 1)*16 + k16*32));
                MMA_F16(sc[2*kf],     qf[k16], kb);
                MMA_F16(sc[2*kf + 1], qf[k16], kb + 2);
            }
        }

        uint32_t pf[4][4];
        #pragma unroll
        for (int f = 0; f < 8; ++f) {
            float p0 = exp2f(sc[f][0]*Cc), p1 = exp2f(sc[f][1]*Cc);
            float p2 = exp2f(sc[f][2]*Cc), p3 = exp2f(sc[f][3]*Cc);
            lA += p0 + p1; lB += p2 + p3;
            int j16 = f >> 1, hf = f & 1;
            pf[j16][hf*2 + 0] = pack_f16x2(p1, p0);
            pf[j16][hf*2 + 1] = pack_f16x2(p3, p2);
        }

        #pragma unroll
        for (int j16 = 0; j16 < 4; ++j16) {
            #pragma unroll
            for (int nfp = 0; nfp < 4; ++nfp) {
                uint32_t vb[4];
                LDSM4T(vb, uV + (uint32_t)((j16*16 + (lane & 7) + ((lane >> 3) & 1)*8)*144
                                           + nfp*32 + (lane >> 4)*16));
                MMA_F16(oa[2*nfp],     pf[j16], vb);
                MMA_F16(oa[2*nfp + 1], pf[j16], vb + 2);
            }
        }
    }

    lA += __shfl_xor_sync(0xffffffffu, lA, 1);
    lA += __shfl_xor_sync(0xffffffffu, lA, 2);
    lB += __shfl_xor_sync(0xffffffffu, lB, 1);
    lB += __shfl_xor_sync(0xffffffffu, lB, 2);

    float iA = 1.f / lA, iB = 1.f / lB;
    int ra = q0 + wid*16 + (lane >> 2);
    #pragma unroll
    for (int f = 0; f < 8; ++f) {
        int col = h*Dd + f*8 + (lane & 3)*2;
        *(uint32_t*)(Oh + (size_t)(b*Tt + ra)*Ee + col)     = pack_f16x2(oa[f][1]*iA, oa[f][0]*iA);
        *(uint32_t*)(Oh + (size_t)(b*Tt + ra + 8)*Ee + col) = pack_f16x2(oa[f][3]*iB, oa[f][2]*iB);
    }
}

// ================= residual + LayerNorm =================
template<int MODE>   // 0: f32 only, 1: + fp16
__global__ __launch_bounds__(128)
void ln_kernel(const float* __restrict__ y, const float* __restrict__ res,
               const float* __restrict__ g, const float* __restrict__ be,
               float* __restrict__ out, __half* __restrict__ outH)
{
    const int row = blockIdx.x;
    const int tid = threadIdx.x;

    float4 v = ((const float4*)(y   + (size_t)row*Ee))[tid];
    float4 r = ((const float4*)(res + (size_t)row*Ee))[tid];
    v.x += r.x; v.y += r.y; v.z += r.z; v.w += r.w;

    float s  = v.x + v.y + v.z + v.w;
    float sq = v.x*v.x + v.y*v.y + v.z*v.z + v.w*v.w;
    #pragma unroll
    for (int o = 16; o > 0; o >>= 1) {
        s  += __shfl_xor_sync(0xffffffffu, s,  o);
        sq += __shfl_xor_sync(0xffffffffu, sq, o);
    }
    __shared__ float ss[4], ssq[4];
    int w = tid >> 5;
    if ((tid & 31) == 0) { ss[w] = s; ssq[w] = sq; }
    __syncthreads();
    s  = ss[0] + ss[1] + ss[2] + ss[3];
    sq = ssq[0] + ssq[1] + ssq[2] + ssq[3];

    const float inv_n = 1.f / (float)Ee;
    float mu  = s * inv_n;
    float var = sq * inv_n - mu*mu;
    float rs  = rsqrtf(var + LN_EPS);

    float4 gg = ((const float4*)g )[tid];
    float4 bb = ((const float4*)be)[tid];
    float4 o;
    o.x = (v.x - mu)*rs*gg.x + bb.x;
    o.y = (v.y - mu)*rs*gg.y + bb.y;
    o.z = (v.z - mu)*rs*gg.z + bb.z;
    o.w = (v.w - mu)*rs*gg.w + bb.w;
    ((float4*)(out + (size_t)row*Ee))[tid] = o;

    if (MODE >= 1) {
        size_t idx = (size_t)row*Ee + tid*4;
        *(uint2*)(outH + idx) = make_uint2(pack_f16x2(o.y, o.x), pack_f16x2(o.w, o.z));
    }
}

// ================= host orchestration =================
extern "C" void kernel_launch(void* const* d_in, const int* in_sizes, int n_in,
                              void* d_out, int out_size)
{
    const float* in[28];
    for (int i = 0; i < 28 && i < n_in; ++i) in[i] = (const float*)d_in[i];

    const float *tgt = in[0], *mem = in[1];
    const float *sWq,*sbq,*sWk,*sbk,*sWv,*sbv,*sWo,*sbo;
    const float *cWq,*cbq,*cWk,*cbk,*cWv,*cbv,*cWo,*cbo;
    const float *fW1,*fb1,*fW2,*fb2,*g1,*be1,*g2,*be2,*g3,*be3;

    bool sig = (in_sizes[3] == Ee);
    if (sig) {
        sWq=in[2];  sbq=in[3];  sWk=in[4];  sbk=in[5];
        sWv=in[6];  sbv=in[7];  sWo=in[8];  sbo=in[9];
        cWq=in[10]; cbq=in[11]; cWk=in[12]; cbk=in[13];
        cWv=in[14]; cbv=in[15]; cWo=in[16]; cbo=in[17];
        fW1=in[18]; fb1=in[19]; fW2=in[20]; fb2=in[21];
        g1=in[22];  be1=in[23]; g2=in[24];  be2=in[25]; g3=in[26]; be3=in[27];
    } else {
        sWq=in[2];  sWk=in[3];  sWv=in[4];  sWo=in[5];
        cWq=in[6];  cWk=in[7];  cWv=in[8];  cWo=in[9];
        sbq=in[10]; sbk=in[11]; sbv=in[12]; sbo=in[13];
        cbq=in[14]; cbk=in[15]; cbv=in[16]; cbo=in[17];
        fW1=in[18]; fb1=in[19]; fW2=in[20]; fb2=in[21];
        g1=in[22];  g2=in[23];  g3=in[24];  be1=in[25]; be2=in[26]; be3=in[27];
    }

    float *Y,*X1,*X2,*BcatS,*BcatC;
    __half *TH,*MH,*QKVb,*QKVc,*OH,*X1H,*X2H,*HfH;
    __half *WcS,*WoS,*WcQ,*WcKV,*WoC,*W1H,*W2H;
    cudaGetSymbolAddress((void**)&Y,    g_Y);
    cudaGetSymbolAddress((void**)&X1,   g_X1);
    cudaGetSymbolAddress((void**)&X2,   g_X2);
    cudaGetSymbolAddress((void**)&BcatS,g_BcatS);
    cudaGetSymbolAddress((void**)&BcatC,g_BcatC);
    cudaGetSymbolAddress((void**)&TH,   g_TH);
    cudaGetSymbolAddress((void**)&MH,   g_MH);
    cudaGetSymbolAddress((void**)&QKVb, g_QKVb);
    cudaGetSymbolAddress((void**)&QKVc, g_QKVc);
    cudaGetSymbolAddress((void**)&OH,   g_OH);
    cudaGetSymbolAddress((void**)&X1H,  g_X1H);
    cudaGetSymbolAddress((void**)&X2H,  g_X2H);
    cudaGetSymbolAddress((void**)&HfH,  g_HfH);
    cudaGetSymbolAddress((void**)&WcS,  g_WcS);
    cudaGetSymbolAddress((void**)&WoS,  g_WoS);
    cudaGetSymbolAddress((void**)&WcQ,  g_WcQ);
    cudaGetSymbolAddress((void**)&WcKV, g_WcKV);
    cudaGetSymbolAddress((void**)&WoC,  g_WoC);
    cudaGetSymbolAddress((void**)&W1H,  g_W1H);
    cudaGetSymbolAddress((void**)&W2H,  g_W2H);

    float* out = (float*)d_out;

    static cudaStream_t s2 = nullptr;
    static cudaEvent_t evF = nullptr, evA = nullptr, evJ = nullptr;
    if (!s2) {
        cudaStreamCreateWithFlags(&s2, cudaStreamNonBlocking);
        cudaEventCreateWithFlags(&evF, cudaEventDisableTiming);
        cudaEventCreateWithFlags(&evA, cudaEventDisableTiming);
        cudaEventCreateWithFlags(&evJ, cudaEventDisableTiming);
    }

    const int SM_B64L = 3 * ((128+128)*144);    // BK64 BM128 S3: 110592
    const int SM_B64S = 3 * (( 64+128)*144);    // BK64 BM64  S3: 82944
    const int SM_AT   = 9216 + 2*18432;         // attention: 46080

    cudaFuncSetAttribute(gemm_pipe<1,0,128,64,3>, cudaFuncAttributeMaxDynamicSharedMemorySize, SM_B64L);
    cudaFuncSetAttribute(gemm_pipe<1,1,128,64,3>, cudaFuncAttributeMaxDynamicSharedMemorySize, SM_B64L);
    cudaFuncSetAttribute(gemm_pipe<1,0, 64,64,3>, cudaFuncAttributeMaxDynamicSharedMemorySize, SM_B64S);
    cudaFuncSetAttribute(gemm_pipe<0,0, 64,64,3>, cudaFuncAttributeMaxDynamicSharedMemorySize, SM_B64S);
    cudaFuncSetAttribute(attn_mma, cudaFuncAttributeMaxDynamicSharedMemorySize, SM_AT);

    const dim3 gAttn(Tt/64, Hh, Bb);   // 512 blocks

    // ---- fork: aux conversions + cross-KV GEMM on s2 ----
    cudaEventRecord(evF, 0);
    cudaStreamWaitEvent(s2, evF, 0);
    conv_aux<<<5380, 256, 0, s2>>>(cWk, cWv, sWo, cWq, cWo, fW1, fW2, cbk, cbv, mem);
    cudaEventRecord(evA, s2);
    gemm_pipe<1,0,128,64,3><<<dim3(8,32), 256, SM_B64L, s2>>>(MH, WcKV, BcatC, 0, QKVc+512, 1024, Ee, 1536);
    cudaEventRecord(evJ, s2);

    // ---- main chain: self-attention block ----
    conv_main<<<2822, 256>>>(sWq, sWk, sWv, sbq, sbk, sbv, tgt);
    gemm_pipe<1,0,128,64,3><<<dim3(12,32), 256, SM_B64L>>>(TH, WcS, BcatS, 0, QKVb, 1536, Ee, 1536);
    attn_mma<<<gAttn, 128, SM_AT>>>(QKVb, OH);
    cudaStreamWaitEvent(0, evA, 0);   // WoS/WcQ/WoC/FFN weights ready
    gemm_pipe<0,0,64,64,3><<<dim3(4,64), 256, SM_B64S>>>(OH, WoS, sbo, Y, 0, Ee, Ee, Ee);
    ln_kernel<1><<<NROWS, 128>>>(Y, tgt, g1, be1, X1, X1H);

    // ---- cross-attention block ----
    gemm_pipe<1,0,64,64,3><<<dim3(4,64), 256, SM_B64S>>>(X1H, WcQ, cbq, 0, QKVc, Ee, Ee, 1536);
    cudaStreamWaitEvent(0, evJ, 0);
    attn_mma<<<gAttn, 128, SM_AT>>>(QKVc, OH);
    gemm_pipe<0,0,64,64,3><<<dim3(4,64), 256, SM_B64S>>>(OH, WoC, cbo, Y, 0, Ee, Ee, Ee);
    ln_kernel<1><<<NROWS, 128>>>(Y, X1, g2, be2, X2, X2H);

    // ---- FFN block (single-term fp16) ----
    gemm_pipe<1,1,128,64,3><<<dim3(16,32), 256, SM_B64L>>>(X2H, W1H, fb1, 0, HfH, Ff, Ee, Ff);
    gemm_pipe<0,0,64,64,3><<<dim3(4,64), 256, SM_B64S>>>(HfH, W2H, fb2, Y, 0, Ee, Ff, Ee);
    ln_kernel<0><<<NROWS, 128>>>(Y, X2, g3, be3, out, 0);
}

// round 14
// speedup vs baseline: 1.3142x; 1.0073x over previous
#include <cuda_runtime.h>
#include <cuda_fp16.h>
#include <cstdint>
#include <math.h>

#define Bb 4
#define Tt 1024
#define Ee 512
#define Hh 8
#define Dd 64
#define Ff 2048
#define NROWS (Bb*Tt)
#define SCALE 0.125f
#define LN_EPS 1e-5f

// ================= device scratch (all 16-bit buffers are fp16) ===========
__device__ __align__(16) float g_Y [NROWS*Ee];
__device__ __align__(16) float g_X1[NROWS*Ee];
__device__ __align__(16) float g_X2[NROWS*Ee];
__device__ __align__(16) float g_BcatS[1536];
__device__ __align__(16) float g_BcatC[1024];
__device__ __align__(16) __half g_TH  [NROWS*Ee];
__device__ __align__(16) __half g_MH  [NROWS*Ee];
__device__ __align__(16) __half g_QKVb[NROWS*1536];   // self QKV
__device__ __align__(16) __half g_QKVc[NROWS*1536];   // cross QKV
__device__ __align__(16) __half g_OH  [NROWS*Ee];
__device__ __align__(16) __half g_YH  [NROWS*Ee];     // Wo output (fp16)
__device__ __align__(16) __half g_X1H [NROWS*Ee];
__device__ __align__(16) __half g_X2H [NROWS*Ee];
__device__ __align__(16) __half g_HfH [NROWS*Ff];
__device__ __align__(16) __half g_WcS [1536*Ee];
__device__ __align__(16) __half g_WoS [Ee*Ee];
__device__ __align__(16) __half g_WcQ [Ee*Ee];
__device__ __align__(16) __half g_WcKV[1024*Ee];
__device__ __align__(16) __half g_WoC [Ee*Ee];
__device__ __align__(16) __half g_W1H [Ee*Ff];
__device__ __align__(16) __half g_W2H [Ff*Ee];

// ================= PTX helpers =================
__device__ __forceinline__ uint32_t smem_u32(const void* p) {
    uint32_t a;
    asm("{ .reg .u64 t; cvta.to.shared.u64 t, %1; cvt.u32.u64 %0, t; }" : "=r"(a) : "l"(p));
    return a;
}
#define LDSM4(r, addr) \
    asm volatile("ldmatrix.sync.aligned.m8n8.x4.shared.b16 {%0,%1,%2,%3}, [%4];" \
        : "=r"((r)[0]), "=r"((r)[1]), "=r"((r)[2]), "=r"((r)[3]) : "r"(addr))
#define LDSM4T(r, addr) \
    asm volatile("ldmatrix.sync.aligned.m8n8.x4.trans.shared.b16 {%0,%1,%2,%3}, [%4];" \
        : "=r"((r)[0]), "=r"((r)[1]), "=r"((r)[2]), "=r"((r)[3]) : "r"(addr))
#define LDSM2(r, addr) \
    asm volatile("ldmatrix.sync.aligned.m8n8.x2.shared.b16 {%0,%1}, [%2];" \
        : "=r"((r)[0]), "=r"((r)[1]) : "r"(addr))
#define MMA_F16(d, a, b) \
    asm volatile("mma.sync.aligned.m16n8k16.row.col.f32.f16.f16.f32 " \
        "{%0,%1,%2,%3}, {%4,%5,%6,%7}, {%8,%9}, {%0,%1,%2,%3};" \
        : "+f"((d)[0]), "+f"((d)[1]), "+f"((d)[2]), "+f"((d)[3]) \
        : "r"((a)[0]), "r"((a)[1]), "r"((a)[2]), "r"((a)[3]), "r"((b)[0]), "r"((b)[1]))
#define CP_ASYNC16(dst, src) \
    asm volatile("cp.async.cg.shared.global [%0], [%1], 16;" :: "r"(dst), "l"(src))
#define CP_COMMIT() asm volatile("cp.async.commit_group;" ::: "memory")
#define CP_WAIT(n)  asm volatile("cp.async.wait_group %0;" :: "n"(n) : "memory")
#define EX2_F16X2(d, x) \
    asm("ex2.approx.f16x2 %0, %1;" : "=r"(d) : "r"(x))
__device__ __forceinline__ uint32_t pack_f16x2(float hi, float lo) {
    __half2 h = __floats2half2_rn(lo, hi);
    return *(uint32_t*)&h;
}

// ================= conversion helpers =================
__device__ __forceinline__ void conv_weight_tile(const float* src, __half* dh,
                                                 int K, int N, int t)
{
    int tn = N >> 5;
    int n0 = (t % tn) * 32, k0 = (t / tn) * 32;
    __shared__ float tile[32][33];
    int tx = threadIdx.x & 31, ty = threadIdx.x >> 5;
    for (int r = ty; r < 32; r += 8)
        tile[r][tx] = src[(size_t)(k0 + r) * N + n0 + tx];
    __syncthreads();
    for (int r = ty; r < 32; r += 8)
        dh[(size_t)(n0 + r) * K + k0 + tx] = __float2half_rn(tile[tx][r]);
}

// critical path: sWq/k/v + self biases + tgt
__global__ __launch_bounds__(256)
void conv_main(const float* sWq, const float* sWk, const float* sWv,
               const float* sbq, const float* sbk, const float* sbv,
               const float* tgt)
{
    int bid = blockIdx.x;
    if (bid < 768) {
        int rg = bid >> 8, t = bid & 255;
        const float* src = rg == 0 ? sWq : (rg == 1 ? sWk : sWv);
        conv_weight_tile(src, g_WcS + (size_t)rg * 512 * 512, 512, 512, t);
        return;
    }
    if (bid < 774) {
        int idx = (bid - 768) * 256 + threadIdx.x;
        const float* s = idx < 512 ? sbq : (idx < 1024 ? sbk : sbv);
        g_BcatS[idx] = s[idx & 511];
        return;
    }
    int i = (bid - 774) * 256 + threadIdx.x;
    float4 v = ((const float4*)tgt)[i];
    ((uint2*)g_TH)[i] = make_uint2(pack_f16x2(v.y, v.x), pack_f16x2(v.w, v.z));
}

// aux stream: cWk/cWv, sWo/cWq/cWo, FFN weights, cross biases, mem
__global__ __launch_bounds__(256)
void conv_aux(const float* cWk, const float* cWv,
              const float* sWo, const float* cWq, const float* cWo,
              const float* fW1, const float* fW2,
              const float* cbk, const float* cbv, const float* mem)
{
    int bid = blockIdx.x;
    if (bid < 512) {
        int rg = bid >> 8, t = bid & 255;
        conv_weight_tile(rg ? cWv : cWk, rg ? g_WcKV + 512*512 : g_WcKV, 512, 512, t);
        return;
    }
    if (bid < 768)  { conv_weight_tile(sWo, g_WoS, 512, 512, bid - 512);  return; }
    if (bid < 1024) { conv_weight_tile(cWq, g_WcQ, 512, 512, bid - 768);  return; }
    if (bid < 1280) { conv_weight_tile(cWo, g_WoC, 512, 512, bid - 1024); return; }
    if (bid < 2304) { conv_weight_tile(fW1, g_W1H, 512, 2048, bid - 1280); return; }
    if (bid < 3328) { conv_weight_tile(fW2, g_W2H, 2048, 512, bid - 2304); return; }
    if (bid < 3332) {
        int idx = (bid - 3328) * 256 + threadIdx.x;
        g_BcatC[idx] = (idx < 512 ? cbk : cbv)[idx & 511];
        return;
    }
    int i = (bid - 3332) * 256 + threadIdx.x;
    float4 v = ((const float4*)mem)[i];
    ((uint2*)g_MH)[i] = make_uint2(pack_f16x2(v.y, v.x), pack_f16x2(v.w, v.z));
}

// ================= cp.async pipelined HMMA GEMM (fp16, single-term) ========
// OMODE: 0 = fp32 out, 1 = fp16 out. BK = K-slab.
template<int OMODE, int RELU, int BM, int BK, int STAGES>
__global__ __launch_bounds__(256)
void gemm_pipe(const __half* __restrict__ Ah, const __half* __restrict__ Bh,
               const float* __restrict__ bias, float* __restrict__ C32,
               __half* __restrict__ C16h,
               int N, int K, int ldc)
{
    constexpr uint32_t ROWBK = (BK == 32) ? 80u : 144u;
    constexpr int CH = BK / 8;
    constexpr int K16 = BK / 16;
    constexpr uint32_t AREG = (uint32_t)BM * ROWBK;
    constexpr uint32_t BREG = 128u * ROWBK;
    constexpr uint32_t STG = AREG + BREG;
    constexpr int MT = BM / 32;
    constexpr int WG = STAGES - 2;
    extern __shared__ char sm[];
    const uint32_t sb = smem_u32(sm);
    const int tid = threadIdx.x, lane = tid & 31, wid = tid >> 5;
    const int wm = wid >> 2, wn = wid & 3;
    const int m0 = blockIdx.y * BM, n0 = blockIdx.x * 128;

    const int l16 = lane & 15;
    const uint32_t a_lsm = sb +
        (uint32_t)((wm*(BM/2) + (lane & 7) + ((lane >> 3) & 1)*8) * ROWBK + (lane >> 4)*16);
    const uint32_t b_lsm = sb + AREG +
        (uint32_t)((wn*32 + (l16 & 7)) * ROWBK + (l16 >> 3)*16);

    float acc[MT][4][4];
    #pragma unroll
    for (int i = 0; i < MT; ++i)
        #pragma unroll
        for (int j = 0; j < 4; ++j) {
            acc[i][j][0] = 0.f; acc[i][j][1] = 0.f;
            acc[i][j][2] = 0.f; acc[i][j][3] = 0.f;
        }

    auto LDGA = [&](int kc, int st) {
        uint32_t base = (uint32_t)st * STG;
        #pragma unroll
        for (int i = 0; i < BM*CH/256; ++i) {
            int c = tid + i*256; int row = c / CH, k8 = c % CH;
            size_t g = (size_t)(m0 + row)*K + (size_t)kc*BK + k8*8;
            CP_ASYNC16(sb + base + row*ROWBK + k8*16, Ah + g);
        }
        #pragma unroll
        for (int i = 0; i < 128*CH/256; ++i) {
            int c = tid + i*256; int row = c / CH, k8 = c % CH;
            size_t g = (size_t)(n0 + row)*K + (size_t)kc*BK + k8*8;
            CP_ASYNC16(sb + base + AREG + row*ROWBK + k8*16, Bh + g);
        }
    };
    auto COMPUTE = [&](int st) {
        const uint32_t bo = (uint32_t)st * STG;
        #pragma unroll
        for (int k16 = 0; k16 < K16; ++k16) {
            uint32_t bh[4][2];
            #pragma unroll
            for (int nt = 0; nt < 4; ++nt)
                LDSM2(bh[nt], b_lsm + bo + nt*8*ROWBK + k16*32);
            #pragma unroll
            for (int mt = 0; mt < MT; ++mt) {
                uint32_t ah[4];
                LDSM4(ah, a_lsm + bo + mt*16*ROWBK + k16*32);
                #pragma unroll
                for (int nt = 0; nt < 4; ++nt)
                    MMA_F16(acc[mt][nt], ah, bh[nt]);
            }
        }
    };

    const int nk = K / BK;
    #pragma unroll
    for (int s = 0; s < STAGES - 1; ++s) {
        if (s < nk) LDGA(s, s);
        CP_COMMIT();
    }
    for (int kc = 0; kc < nk; ++kc) {
        CP_WAIT(WG);
        __syncthreads();
        int ns = kc + STAGES - 1;
        if (ns < nk) LDGA(ns, ns % STAGES);
        CP_COMMIT();
        COMPUTE(kc % STAGES);
    }

    const int gr = lane >> 2, qc = (lane & 3) * 2;
    #pragma unroll
    for (int mt = 0; mt < MT; ++mt) {
        #pragma unroll
        for (int nt = 0; nt < 4; ++nt) {
            int row = m0 + wm*(BM/2) + mt*16 + gr;
            int col = n0 + wn*32 + nt*8 + qc;
            float2 bv = *(const float2*)&bias[col];
            float v0 = acc[mt][nt][0] + bv.x, v1 = acc[mt][nt][1] + bv.y;
            float v2 = acc[mt][nt][2] + bv.x, v3 = acc[mt][nt][3] + bv.y;
            if (RELU) {
                v0 = fmaxf(v0, 0.f); v1 = fmaxf(v1, 0.f);
                v2 = fmaxf(v2, 0.f); v3 = fmaxf(v3, 0.f);
            }
            size_t o0 = (size_t)row * ldc + col;
            size_t o1 = (size_t)(row + 8) * ldc + col;
            if (OMODE == 0) {
                *(float2*)&C32[o0] = make_float2(v0, v1);
                *(float2*)&C32[o1] = make_float2(v2, v3);
            } else {
                *(uint32_t*)(C16h + o0) = pack_f16x2(v1, v0);
                *(uint32_t*)(C16h + o1) = pack_f16x2(v3, v2);
            }
        }
    }
}

// ========== HMMA flash attention =================
// unshifted softmax; exp via ex2.approx.f16x2 (half MUFU ops, direct fp16);
// l accumulated via MMA with an all-ones B fragment (no scalar adds/shuffles).
__global__ __launch_bounds__(128)
void attn_mma(const __half* __restrict__ QKV, __half* __restrict__ Oh)
{
    extern __shared__ char sm[];
    const int b = blockIdx.z, h = blockIdx.y, q0 = blockIdx.x * 64;
    const int tid = threadIdx.x, lane = tid & 31, wid = tid >> 5;
    const uint32_t sb = smem_u32(sm);

    #pragma unroll
    for (int i = 0; i < 4; ++i) {
        int c = tid + i*128; int row = c >> 3, ch = c & 7;
        CP_ASYNC16(sb + row*144 + ch*16,
                   QKV + (size_t)(b*Tt + q0 + row)*1536 + h*Dd + ch*8);
    }
    auto LDKV = [&](int blk, int st) {
        uint32_t base = 9216u + (uint32_t)st * 18432u;
        #pragma unroll
        for (int i = 0; i < 4; ++i) {
            int c = tid + i*128; int row = c >> 3, ch = c & 7;
            size_t g = (size_t)(b*Tt + blk*64 + row)*1536 + h*Dd + ch*8;
            CP_ASYNC16(sb + base + row*144 + ch*16,        QKV + g + 512);
            CP_ASYNC16(sb + base + 9216 + row*144 + ch*16, QKV + g + 1024);
        }
    };
    LDKV(0, 0);
    CP_COMMIT();

    uint32_t qf[4][4];
    float oa[8][4];
    #pragma unroll
    for (int f = 0; f < 8; ++f) { oa[f][0]=0.f; oa[f][1]=0.f; oa[f][2]=0.f; oa[f][3]=0.f; }
    float lacc[4] = {0.f, 0.f, 0.f, 0.f};
    const uint32_t bones[2] = {0x3C003C00u, 0x3C003C00u};   // fp16 1.0 x4
    const float Cc = SCALE * 1.4426950408889634f;

    for (int blk = 0; blk < 16; ++blk) {
        CP_WAIT(0);
        __syncthreads();
        if (blk == 0) {
            #pragma unroll
            for (int k16 = 0; k16 < 4; ++k16)
                LDSM4(qf[k16], sb + (uint32_t)((wid*16 + (lane & 7) + ((lane >> 3) & 1)*8)*144
                                               + (lane >> 4)*16 + k16*32));
        }
        if (blk < 15) { LDKV(blk + 1, (blk + 1) & 1); }
        CP_COMMIT();

        const uint32_t uK = sb + 9216u + (uint32_t)(blk & 1) * 18432u;
        const uint32_t uV = uK + 9216u;

        float sc[8][4];
        #pragma unroll
        for (int f = 0; f < 8; ++f) { sc[f][0]=0.f; sc[f][1]=0.f; sc[f][2]=0.f; sc[f][3]=0.f; }
        #pragma unroll
        for (int k16 = 0; k16 < 4; ++k16) {
            #pragma unroll
            for (int kf = 0; kf < 4; ++kf) {
                uint32_t kb[4];
                LDSM4(kb, uK + (uint32_t)((kf*16 + (lane & 7) + (lane >> 4)*8)*144
                                          + ((lane >> 3) & 1)*16 + k16*32));
                MMA_F16(sc[2*kf],     qf[k16], kb);
                MMA_F16(sc[2*kf + 1], qf[k16], kb + 2);
            }
        }

        // p = 2^(sc*Cc) in fp16 pairs, directly as MMA fragments
        uint32_t pf[4][4];
        #pragma unroll
        for (int f = 0; f < 8; ++f) {
            uint32_t xa = pack_f16x2(sc[f][1]*Cc, sc[f][0]*Cc);
            uint32_t xb = pack_f16x2(sc[f][3]*Cc, sc[f][2]*Cc);
            int j16 = f >> 1, hf = f & 1;
            EX2_F16X2(pf[j16][hf*2 + 0], xa);
            EX2_F16X2(pf[j16][hf*2 + 1], xb);
        }

        // l += P . ones  (tensor pipe; exact sum of the same fp16 p's used below)
        #pragma unroll
        for (int j16 = 0; j16 < 4; ++j16)
            MMA_F16(lacc, pf[j16], bones);

        #pragma unroll
        for (int j16 = 0; j16 < 4; ++j16) {
            #pragma unroll
            for (int nfp = 0; nfp < 4; ++nfp) {
                uint32_t vb[4];
                LDSM4T(vb, uV + (uint32_t)((j16*16 + (lane & 7) + ((lane >> 3) & 1)*8)*144
                                           + nfp*32 + (lane >> 4)*16));
                MMA_F16(oa[2*nfp],     pf[j16], vb);
                MMA_F16(oa[2*nfp + 1], pf[j16], vb + 2);
            }
        }
    }

    float iA = 1.f / lacc[0], iB = 1.f / lacc[2];
    int ra = q0 + wid*16 + (lane >> 2);
    #pragma unroll
    for (int f = 0; f < 8; ++f) {
        int col = h*Dd + f*8 + (lane & 3)*2;
        *(uint32_t*)(Oh + (size_t)(b*Tt + ra)*Ee + col)     = pack_f16x2(oa[f][1]*iA, oa[f][0]*iA);
        *(uint32_t*)(Oh + (size_t)(b*Tt + ra + 8)*Ee + col) = pack_f16x2(oa[f][3]*iB, oa[f][2]*iB);
    }
}

// ================= residual + LayerNorm =================
// MODE: 0 = f32 out only, 1 = +fp16 out.  YIN: 0 = y fp32, 1 = y fp16.
template<int MODE, int YIN>
__global__ __launch_bounds__(128)
void ln_kernel(const float* __restrict__ y32, const __half* __restrict__ y16,
               const float* __restrict__ res,
               const float* __restrict__ g, const float* __restrict__ be,
               float* __restrict__ out, __half* __restrict__ outH)
{
    const int row = blockIdx.x;
    const int tid = threadIdx.x;

    float4 v;
    if (YIN == 0) {
        v = ((const float4*)(y32 + (size_t)row*Ee))[tid];
    } else {
        uint2 yv = ((const uint2*)(y16 + (size_t)row*Ee))[tid];
        __half2 h0 = *(__half2*)&yv.x, h1 = *(__half2*)&yv.y;
        float2 f0 = __half22float2(h0), f1 = __half22float2(h1);
        v = make_float4(f0.x, f0.y, f1.x, f1.y);
    }
    float4 r = ((const float4*)(res + (size_t)row*Ee))[tid];
    v.x += r.x; v.y += r.y; v.z += r.z; v.w += r.w;

    float s  = v.x + v.y + v.z + v.w;
    float sq = v.x*v.x + v.y*v.y + v.z*v.z + v.w*v.w;
    #pragma unroll
    for (int o = 16; o > 0; o >>= 1) {
        s  += __shfl_xor_sync(0xffffffffu, s,  o);
        sq += __shfl_xor_sync(0xffffffffu, sq, o);
    }
    __shared__ float ss[4], ssq[4];
    int w = tid >> 5;
    if ((tid & 31) == 0) { ss[w] = s; ssq[w] = sq; }
    __syncthreads();
    s  = ss[0] + ss[1] + ss[2] + ss[3];
    sq = ssq[0] + ssq[1] + ssq[2] + ssq[3];

    const float inv_n = 1.f / (float)Ee;
    float mu  = s * inv_n;
    float var = sq * inv_n - mu*mu;
    float rs  = rsqrtf(var + LN_EPS);

    float4 gg = ((const float4*)g )[tid];
    float4 bb = ((const float4*)be)[tid];
    float4 o;
    o.x = (v.x - mu)*rs*gg.x + bb.x;
    o.y = (v.y - mu)*rs*gg.y + bb.y;
    o.z = (v.z - mu)*rs*gg.z + bb.z;
    o.w = (v.w - mu)*rs*gg.w + bb.w;
    ((float4*)(out + (size_t)row*Ee))[tid] = o;

    if (MODE >= 1) {
        size_t idx = (size_t)row*Ee + tid*4;
        *(uint2*)(outH + idx) = make_uint2(pack_f16x2(o.y, o.x), pack_f16x2(o.w, o.z));
    }
}

// ================= host orchestration =================
extern "C" void kernel_launch(void* const* d_in, const int* in_sizes, int n_in,
                              void* d_out, int out_size)
{
    const float* in[28];
    for (int i = 0; i < 28 && i < n_in; ++i) in[i] = (const float*)d_in[i];

    const float *tgt = in[0], *mem = in[1];
    const float *sWq,*sbq,*sWk,*sbk,*sWv,*sbv,*sWo,*sbo;
    const float *cWq,*cbq,*cWk,*cbk,*cWv,*cbv,*cWo,*cbo;
    const float *fW1,*fb1,*fW2,*fb2,*g1,*be1,*g2,*be2,*g3,*be3;

    bool sig = (in_sizes[3] == Ee);
    if (sig) {
        sWq=in[2];  sbq=in[3];  sWk=in[4];  sbk=in[5];
        sWv=in[6];  sbv=in[7];  sWo=in[8];  sbo=in[9];
        cWq=in[10]; cbq=in[11]; cWk=in[12]; cbk=in[13];
        cWv=in[14]; cbv=in[15]; cWo=in[16]; cbo=in[17];
        fW1=in[18]; fb1=in[19]; fW2=in[20]; fb2=in[21];
        g1=in[22];  be1=in[23]; g2=in[24];  be2=in[25]; g3=in[26]; be3=in[27];
    } else {
        sWq=in[2];  sWk=in[3];  sWv=in[4];  sWo=in[5];
        cWq=in[6];  cWk=in[7];  cWv=in[8];  cWo=in[9];
        sbq=in[10]; sbk=in[11]; sbv=in[12]; sbo=in[13];
        cbq=in[14]; cbk=in[15]; cbv=in[16]; cbo=in[17];
        fW1=in[18]; fb1=in[19]; fW2=in[20]; fb2=in[21];
        g1=in[22];  g2=in[23];  g3=in[24];  be1=in[25]; be2=in[26]; be3=in[27];
    }

    float *Y,*X1,*X2,*BcatS,*BcatC;
    __half *TH,*MH,*QKVb,*QKVc,*OH,*YH,*X1H,*X2H,*HfH;
    __half *WcS,*WoS,*WcQ,*WcKV,*WoC,*W1H,*W2H;
    cudaGetSymbolAddress((void**)&Y,    g_Y);
    cudaGetSymbolAddress((void**)&X1,   g_X1);
    cudaGetSymbolAddress((void**)&X2,   g_X2);
    cudaGetSymbolAddress((void**)&BcatS,g_BcatS);
    cudaGetSymbolAddress((void**)&BcatC,g_BcatC);
    cudaGetSymbolAddress((void**)&TH,   g_TH);
    cudaGetSymbolAddress((void**)&MH,   g_MH);
    cudaGetSymbolAddress((void**)&QKVb, g_QKVb);
    cudaGetSymbolAddress((void**)&QKVc, g_QKVc);
    cudaGetSymbolAddress((void**)&OH,   g_OH);
    cudaGetSymbolAddress((void**)&YH,   g_YH);
    cudaGetSymbolAddress((void**)&X1H,  g_X1H);
    cudaGetSymbolAddress((void**)&X2H,  g_X2H);
    cudaGetSymbolAddress((void**)&HfH,  g_HfH);
    cudaGetSymbolAddress((void**)&WcS,  g_WcS);
    cudaGetSymbolAddress((void**)&WoS,  g_WoS);
    cudaGetSymbolAddress((void**)&WcQ,  g_WcQ);
    cudaGetSymbolAddress((void**)&WcKV, g_WcKV);
    cudaGetSymbolAddress((void**)&WoC,  g_WoC);
    cudaGetSymbolAddress((void**)&W1H,  g_W1H);
    cudaGetSymbolAddress((void**)&W2H,  g_W2H);

    float* out = (float*)d_out;

    static cudaStream_t s2 = nullptr;
    static cudaEvent_t evF = nullptr, evA = nullptr, evJ = nullptr;
    if (!s2) {
        cudaStreamCreateWithFlags(&s2, cudaStreamNonBlocking);
        cudaEventCreateWithFlags(&evF, cudaEventDisableTiming);
        cudaEventCreateWithFlags(&evA, cudaEventDisableTiming);
        cudaEventCreateWithFlags(&evJ, cudaEventDisableTiming);
    }

    const int SM_B64L = 3 * ((128+128)*144);    // BK64 BM128 S3: 110592
    const int SM_B64S = 4 * (( 64+128)*144);    // BK64 BM64  S4: 110592
    const int SM_AT   = 9216 + 2*18432;         // attention: 46080

    cudaFuncSetAttribute(gemm_pipe<1,0,128,64,3>, cudaFuncAttributeMaxDynamicSharedMemorySize, SM_B64L);
    cudaFuncSetAttribute(gemm_pipe<1,1,128,64,3>, cudaFuncAttributeMaxDynamicSharedMemorySize, SM_B64L);
    cudaFuncSetAttribute(gemm_pipe<1,0, 64,64,4>, cudaFuncAttributeMaxDynamicSharedMemorySize, SM_B64S);
    cudaFuncSetAttribute(gemm_pipe<0,0, 64,64,4>, cudaFuncAttributeMaxDynamicSharedMemorySize, SM_B64S);
    cudaFuncSetAttribute(attn_mma, cudaFuncAttributeMaxDynamicSharedMemorySize, SM_AT);

    const dim3 gAttn(Tt/64, Hh, Bb);   // 512 blocks

    // ---- fork: aux conversions + cross-KV GEMM on s2 ----
    cudaEventRecord(evF, 0);
    cudaStreamWaitEvent(s2, evF, 0);
    conv_aux<<<5380, 256, 0, s2>>>(cWk, cWv, sWo, cWq, cWo, fW1, fW2, cbk, cbv, mem);
    cudaEventRecord(evA, s2);
    gemm_pipe<1,0,128,64,3><<<dim3(8,32), 256, SM_B64L, s2>>>(MH, WcKV, BcatC, 0, QKVc+512, 1024, Ee, 1536);
    cudaEventRecord(evJ, s2);

    // ---- main chain: self-attention block ----
    conv_main<<<2822, 256>>>(sWq, sWk, sWv, sbq, sbk, sbv, tgt);
    gemm_pipe<1,0,128,64,3><<<dim3(12,32), 256, SM_B64L>>>(TH, WcS, BcatS, 0, QKVb, 1536, Ee, 1536);
    attn_mma<<<gAttn, 128, SM_AT>>>(QKVb, OH);
    cudaStreamWaitEvent(0, evA, 0);   // WoS/WcQ/WoC/FFN weights ready
    gemm_pipe<1,0,64,64,4><<<dim3(4,64), 256, SM_B64S>>>(OH, WoS, sbo, 0, YH, Ee, Ee, Ee);
    ln_kernel<1,1><<<NROWS, 128>>>(0, YH, tgt, g1, be1, X1, X1H);

    // ---- cross-attention block ----
    gemm_pipe<1,0,64,64,4><<<dim3(4,64), 256, SM_B64S>>>(X1H, WcQ, cbq, 0, QKVc, Ee, Ee, 1536);
    cudaStreamWaitEvent(0, evJ, 0);
    attn_mma<<<gAttn, 128, SM_AT>>>(QKVc, OH);
    gemm_pipe<1,0,64,64,4><<<dim3(4,64), 256, SM_B64S>>>(OH, WoC, cbo, 0, YH, Ee, Ee, Ee);
    ln_kernel<1,1><<<NROWS, 128>>>(0, YH, X1, g2, be2, X2, X2H);

    // ---- FFN block (single-term fp16) ----
    gemm_pipe<1,1,128,64,3><<<dim3(16,32), 256, SM_B64L>>>(X2H, W1H, fb1, 0, HfH, Ff, Ee, Ff);
    gemm_pipe<0,0,64,64,4><<<dim3(4,64), 256, SM_B64S>>>(HfH, W2H, fb2, Y, 0, Ee, Ff, Ee);
    ln_kernel<0,0><<<NROWS, 128>>>(Y, 0, X2, g3, be3, out, 0);
}

// round 15
// speedup vs baseline: 1.3280x; 1.0105x over previous
#include <cuda_runtime.h>
#include <cuda_fp16.h>
#include <cstdint>
#include <math.h>

#define Bb 4
#define Tt 1024
#define Ee 512
#define Hh 8
#define Dd 64
#define Ff 2048
#define NROWS (Bb*Tt)
#define SCALE 0.125f
#define LN_EPS 1e-5f

// ================= device scratch (all 16-bit buffers are fp16) ===========
__device__ __align__(16) float g_Y [NROWS*Ee];
__device__ __align__(16) float g_X1[NROWS*Ee];
__device__ __align__(16) float g_X2[NROWS*Ee];
__device__ __align__(16) float g_BcatS[1536];
__device__ __align__(16) float g_BcatC[1024];
__device__ __align__(16) __half g_TH  [NROWS*Ee];
__device__ __align__(16) __half g_MH  [NROWS*Ee];
__device__ __align__(16) __half g_QKVb[NROWS*1536];   // self QKV
__device__ __align__(16) __half g_QKVc[NROWS*1536];   // cross QKV
__device__ __align__(16) __half g_OH  [NROWS*Ee];
__device__ __align__(16) __half g_YH  [NROWS*Ee];     // Wo output (fp16)
__device__ __align__(16) __half g_X1H [NROWS*Ee];
__device__ __align__(16) __half g_X2H [NROWS*Ee];
__device__ __align__(16) __half g_HfH [NROWS*Ff];
__device__ __align__(16) __half g_WcS [1536*Ee];
__device__ __align__(16) __half g_WoS [Ee*Ee];
__device__ __align__(16) __half g_WcQ [Ee*Ee];
__device__ __align__(16) __half g_WcKV[1024*Ee];
__device__ __align__(16) __half g_WoC [Ee*Ee];
__device__ __align__(16) __half g_W1H [Ee*Ff];
__device__ __align__(16) __half g_W2H [Ff*Ee];

// ================= PTX helpers =================
__device__ __forceinline__ uint32_t smem_u32(const void* p) {
    uint32_t a;
    asm("{ .reg .u64 t; cvta.to.shared.u64 t, %1; cvt.u32.u64 %0, t; }" : "=r"(a) : "l"(p));
    return a;
}
#define LDSM4(r, addr) \
    asm volatile("ldmatrix.sync.aligned.m8n8.x4.shared.b16 {%0,%1,%2,%3}, [%4];" \
        : "=r"((r)[0]), "=r"((r)[1]), "=r"((r)[2]), "=r"((r)[3]) : "r"(addr))
#define LDSM4T(r, addr) \
    asm volatile("ldmatrix.sync.aligned.m8n8.x4.trans.shared.b16 {%0,%1,%2,%3}, [%4];" \
        : "=r"((r)[0]), "=r"((r)[1]), "=r"((r)[2]), "=r"((r)[3]) : "r"(addr))
#define LDSM2(r, addr) \
    asm volatile("ldmatrix.sync.aligned.m8n8.x2.shared.b16 {%0,%1}, [%2];" \
        : "=r"((r)[0]), "=r"((r)[1]) : "r"(addr))
#define MMA_F16(d, a, b) \
    asm volatile("mma.sync.aligned.m16n8k16.row.col.f32.f16.f16.f32 " \
        "{%0,%1,%2,%3}, {%4,%5,%6,%7}, {%8,%9}, {%0,%1,%2,%3};" \
        : "+f"((d)[0]), "+f"((d)[1]), "+f"((d)[2]), "+f"((d)[3]) \
        : "r"((a)[0]), "r"((a)[1]), "r"((a)[2]), "r"((a)[3]), "r"((b)[0]), "r"((b)[1]))
#define CP_ASYNC16(dst, src) \
    asm volatile("cp.async.cg.shared.global [%0], [%1], 16;" :: "r"(dst), "l"(src))
#define CP_COMMIT() asm volatile("cp.async.commit_group;" ::: "memory")
#define CP_WAIT(n)  asm volatile("cp.async.wait_group %0;" :: "n"(n) : "memory")
#define EX2_F16X2(d, x) \
    asm("ex2.approx.f16x2 %0, %1;" : "=r"(d) : "r"(x))
__device__ __forceinline__ uint32_t pack_f16x2(float hi, float lo) {
    __half2 h = __floats2half2_rn(lo, hi);
    return *(uint32_t*)&h;
}

// ================= conversion helpers =================
__device__ __forceinline__ void conv_weight_tile(const float* src, __half* dh,
                                                 int K, int N, int t)
{
    int tn = N >> 5;
    int n0 = (t % tn) * 32, k0 = (t / tn) * 32;
    __shared__ float tile[32][33];
    int tx = threadIdx.x & 31, ty = threadIdx.x >> 5;
    for (int r = ty; r < 32; r += 8)
        tile[r][tx] = src[(size_t)(k0 + r) * N + n0 + tx];
    __syncthreads();
    for (int r = ty; r < 32; r += 8)
        dh[(size_t)(n0 + r) * K + k0 + tx] = __float2half_rn(tile[tx][r]);
}

// critical path: sWq/k/v + self biases + tgt
__global__ __launch_bounds__(256)
void conv_main(const float* sWq, const float* sWk, const float* sWv,
               const float* sbq, const float* sbk, const float* sbv,
               const float* tgt)
{
    int bid = blockIdx.x;
    if (bid < 768) {
        int rg = bid >> 8, t = bid & 255;
        const float* src = rg == 0 ? sWq : (rg == 1 ? sWk : sWv);
        conv_weight_tile(src, g_WcS + (size_t)rg * 512 * 512, 512, 512, t);
        return;
    }
    if (bid < 774) {
        int idx = (bid - 768) * 256 + threadIdx.x;
        const float* s = idx < 512 ? sbq : (idx < 1024 ? sbk : sbv);
        g_BcatS[idx] = s[idx & 511];
        return;
    }
    int i = (bid - 774) * 256 + threadIdx.x;
    float4 v = ((const float4*)tgt)[i];
    ((uint2*)g_TH)[i] = make_uint2(pack_f16x2(v.y, v.x), pack_f16x2(v.w, v.z));
}

// aux stream: cWk/cWv, sWo/cWq/cWo, FFN weights, cross biases, mem
__global__ __launch_bounds__(256)
void conv_aux(const float* cWk, const float* cWv,
              const float* sWo, const float* cWq, const float* cWo,
              const float* fW1, const float* fW2,
              const float* cbk, const float* cbv, const float* mem)
{
    int bid = blockIdx.x;
    if (bid < 512) {
        int rg = bid >> 8, t = bid & 255;
        conv_weight_tile(rg ? cWv : cWk, rg ? g_WcKV + 512*512 : g_WcKV, 512, 512, t);
        return;
    }
    if (bid < 768)  { conv_weight_tile(sWo, g_WoS, 512, 512, bid - 512);  return; }
    if (bid < 1024) { conv_weight_tile(cWq, g_WcQ, 512, 512, bid - 768);  return; }
    if (bid < 1280) { conv_weight_tile(cWo, g_WoC, 512, 512, bid - 1024); return; }
    if (bid < 2304) { conv_weight_tile(fW1, g_W1H, 512, 2048, bid - 1280); return; }
    if (bid < 3328) { conv_weight_tile(fW2, g_W2H, 2048, 512, bid - 2304); return; }
    if (bid < 3332) {
        int idx = (bid - 3328) * 256 + threadIdx.x;
        g_BcatC[idx] = (idx < 512 ? cbk : cbv)[idx & 511];
        return;
    }
    int i = (bid - 3332) * 256 + threadIdx.x;
    float4 v = ((const float4*)mem)[i];
    ((uint2*)g_MH)[i] = make_uint2(pack_f16x2(v.y, v.x), pack_f16x2(v.w, v.z));
}

// ================= cp.async pipelined HMMA GEMM (fp16, single-term) ========
// Fragment-level software pipelining: A frags ping-pong over mt, B frags over k16.
// OMODE: 0 = fp32 out, 1 = fp16 out.
template<int OMODE, int RELU, int BM, int BK, int STAGES>
__global__ __launch_bounds__(256)
void gemm_pipe(const __half* __restrict__ Ah, const __half* __restrict__ Bh,
               const float* __restrict__ bias, float* __restrict__ C32,
               __half* __restrict__ C16h,
               int N, int K, int ldc)
{
    constexpr uint32_t ROWBK = (BK == 32) ? 80u : 144u;
    constexpr int CH = BK / 8;
    constexpr int K16 = BK / 16;
    constexpr uint32_t AREG = (uint32_t)BM * ROWBK;
    constexpr uint32_t BREG = 128u * ROWBK;
    constexpr uint32_t STG = AREG + BREG;
    constexpr int MT = BM / 32;
    constexpr int WG = STAGES - 2;
    extern __shared__ char sm[];
    const uint32_t sb = smem_u32(sm);
    const int tid = threadIdx.x, lane = tid & 31, wid = tid >> 5;
    const int wm = wid >> 2, wn = wid & 3;
    const int m0 = blockIdx.y * BM, n0 = blockIdx.x * 128;

    const int l16 = lane & 15;
    const uint32_t a_lsm = sb +
        (uint32_t)((wm*(BM/2) + (lane & 7) + ((lane >> 3) & 1)*8) * ROWBK + (lane >> 4)*16);
    const uint32_t b_lsm = sb + AREG +
        (uint32_t)((wn*32 + (l16 & 7)) * ROWBK + (l16 >> 3)*16);

    float acc[MT][4][4];
    #pragma unroll
    for (int i = 0; i < MT; ++i)
        #pragma unroll
        for (int j = 0; j < 4; ++j) {
            acc[i][j][0] = 0.f; acc[i][j][1] = 0.f;
            acc[i][j][2] = 0.f; acc[i][j][3] = 0.f;
        }

    auto LDGA = [&](int kc, int st) {
        uint32_t base = (uint32_t)st * STG;
        #pragma unroll
        for (int i = 0; i < BM*CH/256; ++i) {
            int c = tid + i*256; int row = c / CH, k8 = c % CH;
            size_t g = (size_t)(m0 + row)*K + (size_t)kc*BK + k8*8;
            CP_ASYNC16(sb + base + row*ROWBK + k8*16, Ah + g);
        }
        #pragma unroll
        for (int i = 0; i < 128*CH/256; ++i) {
            int c = tid + i*256; int row = c / CH, k8 = c % CH;
            size_t g = (size_t)(n0 + row)*K + (size_t)kc*BK + k8*8;
            CP_ASYNC16(sb + base + AREG + row*ROWBK + k8*16, Bh + g);
        }
    };

    auto COMPUTE = [&](int st) {
        const uint32_t bo = (uint32_t)st * STG;
        uint32_t bh[2][4][2];     // B frags, ping-pong over k16
        uint32_t ah[2][4];        // A frags, ping-pong over mt

        // preload B(k16=0) and A(mt=0, k16=0)
        #pragma unroll
        for (int nt = 0; nt < 4; ++nt)
            LDSM2(bh[0][nt], b_lsm + bo + nt*8*ROWBK);
        LDSM4(ah[0], a_lsm + bo);

        #pragma unroll
        for (int k16 = 0; k16 < K16; ++k16) {
            const int kb = k16 & 1;
            #pragma unroll
            for (int mt = 0; mt < MT; ++mt) {
                // prefetch next A frag (or first A of next k16)
                if (mt + 1 < MT) {
                    LDSM4(ah[(mt+1) & 1], a_lsm + bo + (mt+1)*16*ROWBK + k16*32);
                } else if (k16 + 1 < K16) {
                    LDSM4(ah[(mt+1) & 1], a_lsm + bo + (k16+1)*32);
                }
                // prefetch next B frags during first mt's MMA batch
                if (mt == 0 && k16 + 1 < K16) {
                    #pragma unroll
                    for (int nt = 0; nt < 4; ++nt)
                        LDSM2(bh[kb ^ 1][nt], b_lsm + bo + nt*8*ROWBK + (k16+1)*32);
                }
                #pragma unroll
                for (int nt = 0; nt < 4; ++nt)
                    MMA_F16(acc[mt][nt], ah[mt & 1], bh[kb][nt]);
            }
        }
    };

    const int nk = K / BK;
    #pragma unroll
    for (int s = 0; s < STAGES - 1; ++s) {
        if (s < nk) LDGA(s, s);
        CP_COMMIT();
    }
    for (int kc = 0; kc < nk; ++kc) {
        CP_WAIT(WG);
        __syncthreads();
        int ns = kc + STAGES - 1;
        if (ns < nk) LDGA(ns, ns % STAGES);
        CP_COMMIT();
        COMPUTE(kc % STAGES);
    }

    const int gr = lane >> 2, qc = (lane & 3) * 2;
    #pragma unroll
    for (int mt = 0; mt < MT; ++mt) {
        #pragma unroll
        for (int nt = 0; nt < 4; ++nt) {
            int row = m0 + wm*(BM/2) + mt*16 + gr;
            int col = n0 + wn*32 + nt*8 + qc;
            float2 bv = *(const float2*)&bias[col];
            float v0 = acc[mt][nt][0] + bv.x, v1 = acc[mt][nt][1] + bv.y;
            float v2 = acc[mt][nt][2] + bv.x, v3 = acc[mt][nt][3] + bv.y;
            if (RELU) {
                v0 = fmaxf(v0, 0.f); v1 = fmaxf(v1, 0.f);
                v2 = fmaxf(v2, 0.f); v3 = fmaxf(v3, 0.f);
            }
            size_t o0 = (size_t)row * ldc + col;
            size_t o1 = (size_t)(row + 8) * ldc + col;
            if (OMODE == 0) {
                *(float2*)&C32[o0] = make_float2(v0, v1);
                *(float2*)&C32[o1] = make_float2(v2, v3);
            } else {
                *(uint32_t*)(C16h + o0) = pack_f16x2(v1, v0);
                *(uint32_t*)(C16h + o1) = pack_f16x2(v3, v2);
            }
        }
    }
}

// ========== HMMA flash attention =================
// unshifted softmax; exp via ex2.approx.f16x2; l via MMA with all-ones B.
__global__ __launch_bounds__(128)
void attn_mma(const __half* __restrict__ QKV, __half* __restrict__ Oh)
{
    extern __shared__ char sm[];
    const int b = blockIdx.z, h = blockIdx.y, q0 = blockIdx.x * 64;
    const int tid = threadIdx.x, lane = tid & 31, wid = tid >> 5;
    const uint32_t sb = smem_u32(sm);

    #pragma unroll
    for (int i = 0; i < 4; ++i) {
        int c = tid + i*128; int row = c >> 3, ch = c & 7;
        CP_ASYNC16(sb + row*144 + ch*16,
                   QKV + (size_t)(b*Tt + q0 + row)*1536 + h*Dd + ch*8);
    }
    auto LDKV = [&](int blk, int st) {
        uint32_t base = 9216u + (uint32_t)st * 18432u;
        #pragma unroll
        for (int i = 0; i < 4; ++i) {
            int c = tid + i*128; int row = c >> 3, ch = c & 7;
            size_t g = (size_t)(b*Tt + blk*64 + row)*1536 + h*Dd + ch*8;
            CP_ASYNC16(sb + base + row*144 + ch*16,        QKV + g + 512);
            CP_ASYNC16(sb + base + 9216 + row*144 + ch*16, QKV + g + 1024);
        }
    };
    LDKV(0, 0);
    CP_COMMIT();

    uint32_t qf[4][4];
    float oa[8][4];
    #pragma unroll
    for (int f = 0; f < 8; ++f) { oa[f][0]=0.f; oa[f][1]=0.f; oa[f][2]=0.f; oa[f][3]=0.f; }
    float lacc[4] = {0.f, 0.f, 0.f, 0.f};
    const uint32_t bones[2] = {0x3C003C00u, 0x3C003C00u};
    const float Cc = SCALE * 1.4426950408889634f;

    for (int blk = 0; blk < 16; ++blk) {
        CP_WAIT(0);
        __syncthreads();
        if (blk == 0) {
            #pragma unroll
            for (int k16 = 0; k16 < 4; ++k16)
                LDSM4(qf[k16], sb + (uint32_t)((wid*16 + (lane & 7) + ((lane >> 3) & 1)*8)*144
                                               + (lane >> 4)*16 + k16*32));
        }
        if (blk < 15) { LDKV(blk + 1, (blk + 1) & 1); }
        CP_COMMIT();

        const uint32_t uK = sb + 9216u + (uint32_t)(blk & 1) * 18432u;
        const uint32_t uV = uK + 9216u;

        float sc[8][4];
        #pragma unroll
        for (int f = 0; f < 8; ++f) { sc[f][0]=0.f; sc[f][1]=0.f; sc[f][2]=0.f; sc[f][3]=0.f; }
        #pragma unroll
        for (int k16 = 0; k16 < 4; ++k16) {
            #pragma unroll
            for (int kf = 0; kf < 4; ++kf) {
                uint32_t kb[4];
                LDSM4(kb, uK + (uint32_t)((kf*16 + (lane & 7) + (lane >> 4)*8)*144
                                          + ((lane >> 3) & 1)*16 + k16*32));
                MMA_F16(sc[2*kf],     qf[k16], kb);
                MMA_F16(sc[2*kf + 1], qf[k16], kb + 2);
            }
        }

        uint32_t pf[4][4];
        #pragma unroll
        for (int f = 0; f < 8; ++f) {
            uint32_t xa = pack_f16x2(sc[f][1]*Cc, sc[f][0]*Cc);
            uint32_t xb = pack_f16x2(sc[f][3]*Cc, sc[f][2]*Cc);
            int j16 = f >> 1, hf = f & 1;
            EX2_F16X2(pf[j16][hf*2 + 0], xa);
            EX2_F16X2(pf[j16][hf*2 + 1], xb);
        }

        #pragma unroll
        for (int j16 = 0; j16 < 4; ++j16)
            MMA_F16(lacc, pf[j16], bones);

        #pragma unroll
        for (int j16 = 0; j16 < 4; ++j16) {
            #pragma unroll
            for (int nfp = 0; nfp < 4; ++nfp) {
                uint32_t vb[4];
                LDSM4T(vb, uV + (uint32_t)((j16*16 + (lane & 7) + ((lane >> 3) & 1)*8)*144
                                           + nfp*32 + (lane >> 4)*16));
                MMA_F16(oa[2*nfp],     pf[j16], vb);
                MMA_F16(oa[2*nfp + 1], pf[j16], vb + 2);
            }
        }
    }

    float iA = 1.f / lacc[0], iB = 1.f / lacc[2];
    int ra = q0 + wid*16 + (lane >> 2);
    #pragma unroll
    for (int f = 0; f < 8; ++f) {
        int col = h*Dd + f*8 + (lane & 3)*2;
        *(uint32_t*)(Oh + (size_t)(b*Tt + ra)*Ee + col)     = pack_f16x2(oa[f][1]*iA, oa[f][0]*iA);
        *(uint32_t*)(Oh + (size_t)(b*Tt + ra + 8)*Ee + col) = pack_f16x2(oa[f][3]*iB, oa[f][2]*iB);
    }
}

// ================= residual + LayerNorm =================
// MODE: 0 = f32 out only, 1 = +fp16 out.  YIN: 0 = y fp32, 1 = y fp16.
template<int MODE, int YIN>
__global__ __launch_bounds__(128)
void ln_kernel(const float* __restrict__ y32, const __half* __restrict__ y16,
               const float* __restrict__ res,
               const float* __restrict__ g, const float* __restrict__ be,
               float* __restrict__ out, __half* __restrict__ outH)
{
    const int row = blockIdx.x;
    const int tid = threadIdx.x;

    float4 v;
    if (YIN == 0) {
        v = ((const float4*)(y32 + (size_t)row*Ee))[tid];
    } else {
        uint2 yv = ((const uint2*)(y16 + (size_t)row*Ee))[tid];
        __half2 h0 = *(__half2*)&yv.x, h1 = *(__half2*)&yv.y;
        float2 f0 = __half22float2(h0), f1 = __half22float2(h1);
        v = make_float4(f0.x, f0.y, f1.x, f1.y);
    }
    float4 r = ((const float4*)(res + (size_t)row*Ee))[tid];
    v.x += r.x; v.y += r.y; v.z += r.z; v.w += r.w;

    float s  = v.x + v.y + v.z + v.w;
    float sq = v.x*v.x + v.y*v.y + v.z*v.z + v.w*v.w;
    #pragma unroll
    for (int o = 16; o > 0; o >>= 1) {
        s  += __shfl_xor_sync(0xffffffffu, s,  o);
        sq += __shfl_xor_sync(0xffffffffu, sq, o);
    }
    __shared__ float ss[4], ssq[4];
    int w = tid >> 5;
    if ((tid & 31) == 0) { ss[w] = s; ssq[w] = sq; }
    __syncthreads();
    s  = ss[0] + ss[1] + ss[2] + ss[3];
    sq = ssq[0] + ssq[1] + ssq[2] + ssq[3];

    const float inv_n = 1.f / (float)Ee;
    float mu  = s * inv_n;
    float var = sq * inv_n - mu*mu;
    float rs  = rsqrtf(var + LN_EPS);

    float4 gg = ((const float4*)g )[tid];
    float4 bb = ((const float4*)be)[tid];
    float4 o;
    o.x = (v.x - mu)*rs*gg.x + bb.x;
    o.y = (v.y - mu)*rs*gg.y + bb.y;
    o.z = (v.z - mu)*rs*gg.z + bb.z;
    o.w = (v.w - mu)*rs*gg.w + bb.w;
    ((float4*)(out + (size_t)row*Ee))[tid] = o;

    if (MODE >= 1) {
        size_t idx = (size_t)row*Ee + tid*4;
        *(uint2*)(outH + idx) = make_uint2(pack_f16x2(o.y, o.x), pack_f16x2(o.w, o.z));
    }
}

// ================= host orchestration =================
extern "C" void kernel_launch(void* const* d_in, const int* in_sizes, int n_in,
                              void* d_out, int out_size)
{
    const float* in[28];
    for (int i = 0; i < 28 && i < n_in; ++i) in[i] = (const float*)d_in[i];

    const float *tgt = in[0], *mem = in[1];
    const float *sWq,*sbq,*sWk,*sbk,*sWv,*sbv,*sWo,*sbo;
    const float *cWq,*cbq,*cWk,*cbk,*cWv,*cbv,*cWo,*cbo;
    const float *fW1,*fb1,*fW2,*fb2,*g1,*be1,*g2,*be2,*g3,*be3;

    bool sig = (in_sizes[3] == Ee);
    if (sig) {
        sWq=in[2];  sbq=in[3];  sWk=in[4];  sbk=in[5];
        sWv=in[6];  sbv=in[7];  sWo=in[8];  sbo=in[9];
        cWq=in[10]; cbq=in[11]; cWk=in[12]; cbk=in[13];
        cWv=in[14]; cbv=in[15]; cWo=in[16]; cbo=in[17];
        fW1=in[18]; fb1=in[19]; fW2=in[20]; fb2=in[21];
        g1=in[22];  be1=in[23]; g2=in[24];  be2=in[25]; g3=in[26]; be3=in[27];
    } else {
        sWq=in[2];  sWk=in[3];  sWv=in[4];  sWo=in[5];
        cWq=in[6];  cWk=in[7];  cWv=in[8];  cWo=in[9];
        sbq=in[10]; sbk=in[11]; sbv=in[12]; sbo=in[13];
        cbq=in[14]; cbk=in[15]; cbv=in[16]; cbo=in[17];
        fW1=in[18]; fb1=in[19]; fW2=in[20]; fb2=in[21];
        g1=in[22];  g2=in[23];  g3=in[24];  be1=in[25]; be2=in[26]; be3=in[27];
    }

    float *Y,*X1,*X2,*BcatS,*BcatC;
    __half *TH,*MH,*QKVb,*QKVc,*OH,*YH,*X1H,*X2H,*HfH;
    __half *WcS,*WoS,*WcQ,*WcKV,*WoC,*W1H,*W2H;
    cudaGetSymbolAddress((void**)&Y,    g_Y);
    cudaGetSymbolAddress((void**)&X1,   g_X1);
    cudaGetSymbolAddress((void**)&X2,   g_X2);
    cudaGetSymbolAddress((void**)&BcatS,g_BcatS);
    cudaGetSymbolAddress((void**)&BcatC,g_BcatC);
    cudaGetSymbolAddress((void**)&TH,   g_TH);
    cudaGetSymbolAddress((void**)&MH,   g_MH);
    cudaGetSymbolAddress((void**)&QKVb, g_QKVb);
    cudaGetSymbolAddress((void**)&QKVc, g_QKVc);
    cudaGetSymbolAddress((void**)&OH,   g_OH);
    cudaGetSymbolAddress((void**)&YH,   g_YH);
    cudaGetSymbolAddress((void**)&X1H,  g_X1H);
    cudaGetSymbolAddress((void**)&X2H,  g_X2H);
    cudaGetSymbolAddress((void**)&HfH,  g_HfH);
    cudaGetSymbolAddress((void**)&WcS,  g_WcS);
    cudaGetSymbolAddress((void**)&WoS,  g_WoS);
    cudaGetSymbolAddress((void**)&WcQ,  g_WcQ);
    cudaGetSymbolAddress((void**)&WcKV, g_WcKV);
    cudaGetSymbolAddress((void**)&WoC,  g_WoC);
    cudaGetSymbolAddress((void**)&W1H,  g_W1H);
    cudaGetSymbolAddress((void**)&W2H,  g_W2H);

    float* out = (float*)d_out;

    static cudaStream_t s2 = nullptr;
    static cudaEvent_t evF = nullptr, evA = nullptr, evJ = nullptr;
    if (!s2) {
        cudaStreamCreateWithFlags(&s2, cudaStreamNonBlocking);
        cudaEventCreateWithFlags(&evF, cudaEventDisableTiming);
        cudaEventCreateWithFlags(&evA, cudaEventDisableTiming);
        cudaEventCreateWithFlags(&evJ, cudaEventDisableTiming);
    }

    const int SM_B64L = 3 * ((128+128)*144);    // BK64 BM128 S3: 110592
    const int SM_B64S = 4 * (( 64+128)*144);    // BK64 BM64  S4: 110592
    const int SM_AT   = 9216 + 2*18432;         // attention: 46080

    cudaFuncSetAttribute(gemm_pipe<1,0,128,64,3>, cudaFuncAttributeMaxDynamicSharedMemorySize, SM_B64L);
    cudaFuncSetAttribute(gemm_pipe<1,1,128,64,3>, cudaFuncAttributeMaxDynamicSharedMemorySize, SM_B64L);
    cudaFuncSetAttribute(gemm_pipe<1,0, 64,64,4>, cudaFuncAttributeMaxDynamicSharedMemorySize, SM_B64S);
    cudaFuncSetAttribute(gemm_pipe<0,0, 64,64,4>, cudaFuncAttributeMaxDynamicSharedMemorySize, SM_B64S);
    cudaFuncSetAttribute(attn_mma, cudaFuncAttributeMaxDynamicSharedMemorySize, SM_AT);

    const dim3 gAttn(Tt/64, Hh, Bb);   // 512 blocks

    // ---- fork: aux conversions + cross-KV GEMM on s2 ----
    cudaEventRecord(evF, 0);
    cudaStreamWaitEvent(s2, evF, 0);
    conv_aux<<<5380, 256, 0, s2>>>(cWk, cWv, sWo, cWq, cWo, fW1, fW2, cbk, cbv, mem);
    cudaEventRecord(evA, s2);
    gemm_pipe<1,0,128,64,3><<<dim3(8,32), 256, SM_B64L, s2>>>(MH, WcKV, BcatC, 0, QKVc+512, 1024, Ee, 1536);
    cudaEventRecord(evJ, s2);

    // ---- main chain: self-attention block ----
    conv_main<<<2822, 256>>>(sWq, sWk, sWv, sbq, sbk, sbv, tgt);
    gemm_pipe<1,0,128,64,3><<<dim3(12,32), 256, SM_B64L>>>(TH, WcS, BcatS, 0, QKVb, 1536, Ee, 1536);
    attn_mma<<<gAttn, 128, SM_AT>>>(QKVb, OH);
    cudaStreamWaitEvent(0, evA, 0);
    gemm_pipe<1,0,64,64,4><<<dim3(4,64), 256, SM_B64S>>>(OH, WoS, sbo, 0, YH, Ee, Ee, Ee);
    ln_kernel<1,1><<<NROWS, 128>>>(0, YH, tgt, g1, be1, X1, X1H);

    // ---- cross-attention block ----
    gemm_pipe<1,0,64,64,4><<<dim3(4,64), 256, SM_B64S>>>(X1H, WcQ, cbq, 0, QKVc, Ee, Ee, 1536);
    cudaStreamWaitEvent(0, evJ, 0);
    attn_mma<<<gAttn, 128, SM_AT>>>(QKVc, OH);
    gemm_pipe<1,0,64,64,4><<<dim3(4,64), 256, SM_B64S>>>(OH, WoC, cbo, 0, YH, Ee, Ee, Ee);
    ln_kernel<1,1><<<NROWS, 128>>>(0, YH, X1, g2, be2, X2, X2H);

    // ---- FFN block (single-term fp16) ----
    gemm_pipe<1,1,128,64,3><<<dim3(16,32), 256, SM_B64L>>>(X2H, W1H, fb1, 0, HfH, Ff, Ee, Ff);
    gemm_pipe<0,0,64,64,4><<<dim3(4,64), 256, SM_B64S>>>(HfH, W2H, fb2, Y, 0, Ee, Ff, Ee);
    ln_kernel<0,0><<<NROWS, 128>>>(Y, 0, X2, g3, be3, out, 0);
}